// round 1
// baseline (speedup 1.0000x reference)
#include <cuda_runtime.h>
#include <cstdint>

#define BB   2
#define NN   2048
#define DIMC 1024
#define HH   16
#define HD   64
#define MROWS (BB*NN)     // 4096
#define AST  68           // attention smem row stride (pad 4)

// Scratch (allocation-free requirement): head-major (b,h,n,d) buffers.
__device__ float g_q[BB*HH*NN*HD];
__device__ float g_k[BB*HH*NN*HD];
__device__ float g_v[BB*HH*NN*HD];
__device__ float g_o[BB*HH*NN*HD];

// ---------------------------------------------------------------------------
// Kernel 1: fused QKV projection.  Y[4096, 3072] = X @ [Wq|Wk|Wv] + [bq|bk|bv]
// Epilogue scatters to per-head q/k/v buffers with the interleaved-192 mapping:
//   concat channel c -> head h=c/192, t=c%192; t<64 -> Q, t<128 -> K, else V.
// ---------------------------------------------------------------------------
__global__ __launch_bounds__(256) void qkv_gemm(
    const float* __restrict__ x,
    const float* __restrict__ Wq, const float* __restrict__ bq,
    const float* __restrict__ Wk, const float* __restrict__ bk,
    const float* __restrict__ Wv, const float* __restrict__ bv)
{
    __shared__ float As[16][132];   // A transposed: As[k][m], padded
    __shared__ float Bs[16][128];
    const int tid = threadIdx.x;
    const int tx  = tid & 15, ty = tid >> 4;
    const int m0  = blockIdx.y * 128;
    const int c0  = blockIdx.x * 128;

    const float* W; const float* bias;
    int j0;
    if (c0 < DIMC)        { W = Wq; bias = bq; j0 = c0; }
    else if (c0 < 2*DIMC) { W = Wk; bias = bk; j0 = c0 - DIMC; }
    else                  { W = Wv; bias = bv; j0 = c0 - 2*DIMC; }

    float acc[8][8];
    #pragma unroll
    for (int i = 0; i < 8; i++)
        #pragma unroll
        for (int j = 0; j < 8; j++) acc[i][j] = 0.f;

    for (int k0 = 0; k0 < DIMC; k0 += 16) {
        #pragma unroll
        for (int t = 0; t < 2; t++) {
            int i = tid + t*256;          // 0..511 float4s
            int r = i >> 2, kk4 = i & 3;
            float4 a = *(const float4*)(x + (size_t)(m0 + r)*DIMC + k0 + kk4*4);
            As[kk4*4+0][r] = a.x; As[kk4*4+1][r] = a.y;
            As[kk4*4+2][r] = a.z; As[kk4*4+3][r] = a.w;
        }
        #pragma unroll
        for (int t = 0; t < 2; t++) {
            int i = tid + t*256;
            int kk = i >> 5, c4 = i & 31;
            *(float4*)&Bs[kk][c4*4] =
                *(const float4*)(W + (size_t)(k0+kk)*DIMC + j0 + c4*4);
        }
        __syncthreads();
        #pragma unroll
        for (int kk = 0; kk < 16; kk++) {
            float a[8], b[8];
            *(float4*)&a[0] = *(float4*)&As[kk][ty*8];
            *(float4*)&a[4] = *(float4*)&As[kk][ty*8+4];
            *(float4*)&b[0] = *(float4*)&Bs[kk][tx*8];
            *(float4*)&b[4] = *(float4*)&Bs[kk][tx*8+4];
            #pragma unroll
            for (int i = 0; i < 8; i++)
                #pragma unroll
                for (int j = 0; j < 8; j++)
                    acc[i][j] = fmaf(a[i], b[j], acc[i][j]);
        }
        __syncthreads();
    }

    #pragma unroll
    for (int i = 0; i < 8; i++) {
        int m  = m0 + ty*8 + i;
        int bz = m >> 11;          // / NN
        int n  = m & (NN-1);
        #pragma unroll
        for (int j = 0; j < 8; j++) {
            int c = c0 + tx*8 + j;
            float v = acc[i][j] + bias[j0 + tx*8 + j];
            int h = c / 192, t = c % 192, d = t & 63;
            float* dst = (t < 64) ? g_q : (t < 128) ? g_k : g_v;
            dst[(((size_t)bz*HH + h)*NN + n)*HD + d] = v;
        }
    }
}

// ---------------------------------------------------------------------------
// Kernel 2: per-head LayerNorm + RoPE (in place).  One warp per 64-elem row.
// which: 0 -> g_q, 1 -> g_k.
// ---------------------------------------------------------------------------
__global__ __launch_bounds__(256) void ln_rope(
    int which,
    const float* __restrict__ nw, const float* __restrict__ nb,
    const float* __restrict__ cosb, const float* __restrict__ sinb)
{
    int warp = (blockIdx.x * blockDim.x + threadIdx.x) >> 5;
    int lane = threadIdx.x & 31;
    // warp = ((b*HH + h)*NN + n)
    int bz = warp / (HH*NN);
    int n  = warp & (NN-1);

    float* row = (which ? g_k : g_q) + (size_t)warp * HD;
    float x1 = row[lane], x2 = row[lane + 32];
    float sum = x1 + x2;
    float sq  = x1*x1 + x2*x2;
    #pragma unroll
    for (int o = 16; o; o >>= 1) {
        sum += __shfl_xor_sync(0xffffffffu, sum, o);
        sq  += __shfl_xor_sync(0xffffffffu, sq,  o);
    }
    float mean = sum * (1.f/64.f);
    float var  = sq  * (1.f/64.f) - mean*mean;
    float inv  = rsqrtf(var + 1e-6f);
    float y1 = (x1 - mean) * inv * nw[lane]      + nb[lane];
    float y2 = (x2 - mean) * inv * nw[lane + 32] + nb[lane + 32];

    size_t rbase = ((size_t)bz*NN + n) * HD;
    float c1 = cosb[rbase + lane],      s1 = sinb[rbase + lane];
    float c2 = cosb[rbase + lane + 32], s2 = sinb[rbase + lane + 32];
    row[lane]      = y1*c1 - y2*s1;   // d < 32: rotate_half = -x[d+32]
    row[lane + 32] = y2*c2 + y1*s2;   // d >= 32: rotate_half = x[d-32]
}

// ---------------------------------------------------------------------------
// Kernel 3: flash-style attention.  Block = (b,h) x 64 q-rows, 256 threads,
// 16x16 thread grid, 4x4 micro-tiles.  Online softmax via 16-lane shuffles.
// Dynamic smem: Qt, Kt (d-major, transposed), Vs, Ps  — each 64 x AST floats.
// ---------------------------------------------------------------------------
__global__ __launch_bounds__(256) void attn_kernel()
{
    extern __shared__ float smem[];
    float* Qt = smem;
    float* Kt = smem + 64*AST;
    float* Vs = smem + 2*64*AST;
    float* Ps = smem + 3*64*AST;

    const int tid = threadIdx.x;
    const int tx  = tid & 15, ty = tid >> 4;
    const int bh  = blockIdx.y;
    const int q0  = blockIdx.x * 64;
    const float* qb = g_q + (size_t)bh * NN * HD;
    const float* kb = g_k + (size_t)bh * NN * HD;
    const float* vb = g_v + (size_t)bh * NN * HD;

    // Load Q tile, pre-scaled by HD^-0.5, transposed: Qt[d][r]
    #pragma unroll
    for (int t = 0; t < 4; t++) {
        int i = tid + t*256;          // 0..1023 float4s
        int r = i >> 4, d4 = i & 15;
        float4 v = *(const float4*)(qb + (size_t)(q0 + r)*HD + d4*4);
        Qt[(d4*4+0)*AST + r] = v.x * 0.125f;
        Qt[(d4*4+1)*AST + r] = v.y * 0.125f;
        Qt[(d4*4+2)*AST + r] = v.z * 0.125f;
        Qt[(d4*4+3)*AST + r] = v.w * 0.125f;
    }

    float m_i[4], l_i[4], acc[4][4];
    #pragma unroll
    for (int i = 0; i < 4; i++) {
        m_i[i] = -1e30f; l_i[i] = 0.f;
        #pragma unroll
        for (int j = 0; j < 4; j++) acc[i][j] = 0.f;
    }

    for (int kt = 0; kt < NN/64; kt++) {
        const int k0 = kt * 64;
        // Load K (transposed -> Kt[d][c]) and V (row-major -> Vs[c][d])
        #pragma unroll
        for (int t = 0; t < 4; t++) {
            int i = tid + t*256;
            int c = i >> 4, d4 = i & 15;
            float4 kv = *(const float4*)(kb + (size_t)(k0 + c)*HD + d4*4);
            Kt[(d4*4+0)*AST + c] = kv.x;
            Kt[(d4*4+1)*AST + c] = kv.y;
            Kt[(d4*4+2)*AST + c] = kv.z;
            Kt[(d4*4+3)*AST + c] = kv.w;
            float4 vv = *(const float4*)(vb + (size_t)(k0 + c)*HD + d4*4);
            *(float4*)&Vs[c*AST + d4*4] = vv;
        }
        __syncthreads();

        // S = Q @ K^T  (inner dim d = 64)
        float s[4][4];
        #pragma unroll
        for (int i = 0; i < 4; i++)
            #pragma unroll
            for (int j = 0; j < 4; j++) s[i][j] = 0.f;
        #pragma unroll 16
        for (int d = 0; d < 64; d++) {
            float4 qa = *(float4*)&Qt[d*AST + ty*4];
            float4 ka = *(float4*)&Kt[d*AST + tx*4];
            float aq[4] = {qa.x, qa.y, qa.z, qa.w};
            float ak[4] = {ka.x, ka.y, ka.z, ka.w};
            #pragma unroll
            for (int i = 0; i < 4; i++)
                #pragma unroll
                for (int j = 0; j < 4; j++)
                    s[i][j] = fmaf(aq[i], ak[j], s[i][j]);
        }

        // Online softmax update (per q-row, reduced over the 16 tx lanes)
        #pragma unroll
        for (int i = 0; i < 4; i++) {
            float tm = fmaxf(fmaxf(s[i][0], s[i][1]), fmaxf(s[i][2], s[i][3]));
            #pragma unroll
            for (int o = 8; o; o >>= 1)
                tm = fmaxf(tm, __shfl_xor_sync(0xffffffffu, tm, o));
            float m_new = fmaxf(m_i[i], tm);
            float alpha = __expf(m_i[i] - m_new);
            float rs = 0.f;
            #pragma unroll
            for (int j = 0; j < 4; j++) {
                s[i][j] = __expf(s[i][j] - m_new);
                rs += s[i][j];
            }
            #pragma unroll
            for (int o = 8; o; o >>= 1)
                rs += __shfl_xor_sync(0xffffffffu, rs, o);
            l_i[i] = l_i[i] * alpha + rs;
            m_i[i] = m_new;
            #pragma unroll
            for (int j = 0; j < 4; j++) acc[i][j] *= alpha;
        }

        // Stage P to smem for the P @ V GEMM
        #pragma unroll
        for (int i = 0; i < 4; i++)
            #pragma unroll
            for (int j = 0; j < 4; j++)
                Ps[(ty*4+i)*AST + tx*4 + j] = s[i][j];
        __syncthreads();

        // O += P @ V  (inner dim c = 64)
        #pragma unroll 8
        for (int c = 0; c < 64; c++) {
            float4 va = *(float4*)&Vs[c*AST + tx*4];
            float av[4] = {va.x, va.y, va.z, va.w};
            float pa[4];
            #pragma unroll
            for (int i = 0; i < 4; i++) pa[i] = Ps[(ty*4+i)*AST + c];
            #pragma unroll
            for (int i = 0; i < 4; i++)
                #pragma unroll
                for (int j = 0; j < 4; j++)
                    acc[i][j] = fmaf(pa[i], av[j], acc[i][j]);
        }
        __syncthreads();   // protect Kt/Vs/Ps before next tile load
    }

    // Finalize and store
    #pragma unroll
    for (int i = 0; i < 4; i++) {
        float invl = 1.f / l_i[i];
        #pragma unroll
        for (int j = 0; j < 4; j++)
            g_o[((size_t)bh*NN + q0 + ty*4 + i)*HD + tx*4 + j] = acc[i][j] * invl;
    }
}

// ---------------------------------------------------------------------------
// Kernel 4: output projection.  out[m, :] = O_flat[m, :] @ Wo + bo,
// with A gathered from the head-major attention output on the fly.
// ---------------------------------------------------------------------------
__global__ __launch_bounds__(256) void out_gemm(
    const float* __restrict__ Wo, const float* __restrict__ bo,
    float* __restrict__ out)
{
    __shared__ float As[16][132];
    __shared__ float Bs[16][128];
    const int tid = threadIdx.x;
    const int tx  = tid & 15, ty = tid >> 4;
    const int m0  = blockIdx.y * 128;
    const int c0  = blockIdx.x * 128;

    float acc[8][8];
    #pragma unroll
    for (int i = 0; i < 8; i++)
        #pragma unroll
        for (int j = 0; j < 8; j++) acc[i][j] = 0.f;

    for (int k0 = 0; k0 < DIMC; k0 += 16) {
        #pragma unroll
        for (int t = 0; t < 2; t++) {
            int i = tid + t*256;
            int r = i >> 2, kk4 = i & 3;
            int m = m0 + r;
            int bz = m >> 11, n = m & (NN-1);
            int k = k0 + kk4*4;
            int h = k >> 6, d = k & 63;      // 4 consecutive d within one head
            float4 a = *(const float4*)(g_o + (((size_t)bz*HH + h)*NN + n)*HD + d);
            As[kk4*4+0][r] = a.x; As[kk4*4+1][r] = a.y;
            As[kk4*4+2][r] = a.z; As[kk4*4+3][r] = a.w;
        }
        #pragma unroll
        for (int t = 0; t < 2; t++) {
            int i = tid + t*256;
            int kk = i >> 5, c4 = i & 31;
            *(float4*)&Bs[kk][c4*4] =
                *(const float4*)(Wo + (size_t)(k0+kk)*DIMC + c0 + c4*4);
        }
        __syncthreads();
        #pragma unroll
        for (int kk = 0; kk < 16; kk++) {
            float a[8], b[8];
            *(float4*)&a[0] = *(float4*)&As[kk][ty*8];
            *(float4*)&a[4] = *(float4*)&As[kk][ty*8+4];
            *(float4*)&b[0] = *(float4*)&Bs[kk][tx*8];
            *(float4*)&b[4] = *(float4*)&Bs[kk][tx*8+4];
            #pragma unroll
            for (int i = 0; i < 8; i++)
                #pragma unroll
                for (int j = 0; j < 8; j++)
                    acc[i][j] = fmaf(a[i], b[j], acc[i][j]);
        }
        __syncthreads();
    }

    #pragma unroll
    for (int i = 0; i < 8; i++) {
        int m = m0 + ty*8 + i;
        #pragma unroll
        for (int j = 0; j < 8; j++) {
            int c = c0 + tx*8 + j;
            out[(size_t)m*DIMC + c] = acc[i][j] + bo[c];
        }
    }
}

// ---------------------------------------------------------------------------
extern "C" void kernel_launch(void* const* d_in, const int* in_sizes, int n_in,
                              void* d_out, int out_size)
{
    const float* x   = (const float*)d_in[0];
    const float* rc  = (const float*)d_in[1];
    const float* rs  = (const float*)d_in[2];
    const float* Wq  = (const float*)d_in[3];
    const float* bq  = (const float*)d_in[4];
    const float* Wk  = (const float*)d_in[5];
    const float* bk  = (const float*)d_in[6];
    const float* Wv  = (const float*)d_in[7];
    const float* bv  = (const float*)d_in[8];
    const float* qnw = (const float*)d_in[9];
    const float* qnb = (const float*)d_in[10];
    const float* knw = (const float*)d_in[11];
    const float* knb = (const float*)d_in[12];
    const float* Wo  = (const float*)d_in[13];
    const float* bo  = (const float*)d_in[14];
    float* out = (float*)d_out;

    const int attn_smem = 4 * 64 * AST * (int)sizeof(float);   // 69632 B
    cudaFuncSetAttribute(attn_kernel,
                         cudaFuncAttributeMaxDynamicSharedMemorySize, attn_smem);

    qkv_gemm<<<dim3(24, 32), 256>>>(x, Wq, bq, Wk, bk, Wv, bv);

    const int rows = BB*HH*NN;                 // 65536 warp-rows
    ln_rope<<<rows/8, 256>>>(0, qnw, qnb, rc, rs);
    ln_rope<<<rows/8, 256>>>(1, knw, knb, rc, rs);

    attn_kernel<<<dim3(NN/64, BB*HH), 256, attn_smem>>>();

    out_gemm<<<dim3(8, 32), 256>>>(Wo, bo, out);
}

// round 4
// speedup vs baseline: 1.6605x; 1.6605x over previous
#include <cuda_runtime.h>
#include <cstdint>

#define BB   2
#define NN   2048
#define DIMC 1024
#define HH   16
#define HD   64

// Scratch (allocation-free requirement)
__device__ float g_q[BB*HH*NN*HD];
__device__ float g_k[BB*HH*NN*HD];
__device__ float g_v[BB*HH*NN*HD];
__device__ float g_o[BB*HH*NN*HD];
__device__ float g_wt[3*DIMC*DIMC];    // transposed [Wq|Wk|Wv]
__device__ float g_wo_t[DIMC*DIMC];    // transposed Wo

// ---------------------------------------------------------------------------
__device__ __forceinline__ float tf32r(float x) {
    uint32_t u;
    asm("cvt.rna.tf32.f32 %0, %1;" : "=r"(u) : "f"(x));
    return __uint_as_float(u);
}

#define MMA_TF32(c, a0, a1, a2, a3, b0, b1)                                   \
    asm volatile(                                                             \
        "mma.sync.aligned.m16n8k8.row.col.f32.tf32.tf32.f32 "                 \
        "{%0,%1,%2,%3}, {%4,%5,%6,%7}, {%8,%9}, {%0,%1,%2,%3};"               \
        : "+f"((c)[0]), "+f"((c)[1]), "+f"((c)[2]), "+f"((c)[3])              \
        : "r"(__float_as_uint(a0)), "r"(__float_as_uint(a1)),                 \
          "r"(__float_as_uint(a2)), "r"(__float_as_uint(a3)),                 \
          "r"(__float_as_uint(b0)), "r"(__float_as_uint(b1)))

// ---------------------------------------------------------------------------
// Weight transpose: dst[c][k] = src[k][c], 1024x1024.
// ---------------------------------------------------------------------------
__global__ __launch_bounds__(256) void tr_w(const float* __restrict__ src,
                                            float* __restrict__ dst)
{
    __shared__ float t[32][33];
    int tx = threadIdx.x & 31, ty = threadIdx.x >> 5;
    int cb = blockIdx.x * 32, kb = blockIdx.y * 32;
    #pragma unroll
    for (int r = 0; r < 4; r++)
        t[ty + 8*r][tx] = src[(size_t)(kb + ty + 8*r)*DIMC + cb + tx];
    __syncthreads();
    #pragma unroll
    for (int r = 0; r < 4; r++)
        dst[(size_t)(cb + ty + 8*r)*DIMC + kb + tx] = t[tx][ty + 8*r];
}

// ---------------------------------------------------------------------------
// tf32 mma.sync GEMM: 128x128 tile, K=1024.  8 warps (4 m x 2 n),
// warp tile 32x64 = 2 mtiles x 8 ntiles of m16n8k8.
// mode 0: A = x, B = g_wt (3072 rows), scatter epilogue -> g_q/g_k/g_v
// mode 1: A = gathered g_o, B = g_wo_t, epilogue -> out (+bo)
// ---------------------------------------------------------------------------
__global__ __launch_bounds__(256) void mm_mma(
    int mode,
    const float* __restrict__ x,
    const float* __restrict__ bq, const float* __restrict__ bk,
    const float* __restrict__ bv, const float* __restrict__ bo,
    float* __restrict__ out)
{
    __shared__ float As[128*36];
    __shared__ float Bs[128*36];
    const int tid = threadIdx.x, lane = tid & 31, w = tid >> 5;
    const int wm = w & 3, wn = w >> 2;
    const int m0 = blockIdx.y * 128, c0 = blockIdx.x * 128;
    const float* Bsrc = (mode == 0) ? g_wt : g_wo_t;

    float acc[2][8][4];
    #pragma unroll
    for (int mt = 0; mt < 2; mt++)
        #pragma unroll
        for (int nt = 0; nt < 8; nt++)
            #pragma unroll
            for (int e = 0; e < 4; e++) acc[mt][nt][e] = 0.f;

    for (int kc = 0; kc < DIMC/32; kc++) {
        const int k0 = kc * 32;
        #pragma unroll
        for (int i = 0; i < 4; i++) {
            int idx = tid + i*256;          // 0..1023 float4 slots
            int r = idx >> 3, c4 = idx & 7;
            float4 a;
            if (mode == 0) {
                a = *(const float4*)(x + (size_t)(m0 + r)*DIMC + k0 + c4*4);
            } else {
                int m = m0 + r, bz = m >> 11, n = m & (NN-1);
                int k = k0 + c4*4, h = k >> 6, d = k & 63;
                a = *(const float4*)(g_o + (((size_t)bz*HH + h)*NN + n)*HD + d);
            }
            float* pa = &As[r*36 + c4*4];
            pa[0] = tf32r(a.x); pa[1] = tf32r(a.y);
            pa[2] = tf32r(a.z); pa[3] = tf32r(a.w);
            float4 wv = *(const float4*)(Bsrc + (size_t)(c0 + r)*DIMC + k0 + c4*4);
            float* pb = &Bs[r*36 + c4*4];
            pb[0] = tf32r(wv.x); pb[1] = tf32r(wv.y);
            pb[2] = tf32r(wv.z); pb[3] = tf32r(wv.w);
        }
        __syncthreads();
        #pragma unroll
        for (int ks = 0; ks < 4; ks++) {
            const int kk = ks * 8;
            float a[2][4];
            #pragma unroll
            for (int mt = 0; mt < 2; mt++) {
                int rm = wm*32 + mt*16 + (lane >> 2);
                a[mt][0] = As[rm*36      + kk + (lane & 3)];
                a[mt][1] = As[(rm+8)*36  + kk + (lane & 3)];
                a[mt][2] = As[rm*36      + kk + (lane & 3) + 4];
                a[mt][3] = As[(rm+8)*36  + kk + (lane & 3) + 4];
            }
            #pragma unroll
            for (int nt = 0; nt < 8; nt++) {
                int cn = wn*64 + nt*8 + (lane >> 2);
                float b0 = Bs[cn*36 + kk + (lane & 3)];
                float b1 = Bs[cn*36 + kk + (lane & 3) + 4];
                MMA_TF32(acc[0][nt], a[0][0], a[0][1], a[0][2], a[0][3], b0, b1);
                MMA_TF32(acc[1][nt], a[1][0], a[1][1], a[1][2], a[1][3], b0, b1);
            }
        }
        __syncthreads();
    }

    // Epilogue
    #pragma unroll
    for (int mt = 0; mt < 2; mt++) {
        int r_lo = m0 + wm*32 + mt*16 + (lane >> 2);
        int r_hi = r_lo + 8;
        #pragma unroll
        for (int nt = 0; nt < 8; nt++) {
            int c = c0 + wn*64 + nt*8 + (lane & 3)*2;
            if (mode == 0) {
                #pragma unroll
                for (int e = 0; e < 4; e++) {
                    int cc = c + (e & 1);
                    int m  = (e < 2) ? r_lo : r_hi;
                    int bz = m >> 11, n = m & (NN-1);
                    float bias = (cc < DIMC) ? bq[cc]
                               : (cc < 2*DIMC) ? bk[cc - DIMC] : bv[cc - 2*DIMC];
                    float v = acc[mt][nt][e] + bias;
                    int h = cc / 192, t = cc % 192, d = t & 63;
                    float* dst = (t < 64) ? g_q : (t < 128) ? g_k : g_v;
                    dst[(((size_t)bz*HH + h)*NN + n)*HD + d] = v;
                }
            } else {
                float2 lo = make_float2(acc[mt][nt][0] + bo[c],
                                        acc[mt][nt][1] + bo[c+1]);
                float2 hi = make_float2(acc[mt][nt][2] + bo[c],
                                        acc[mt][nt][3] + bo[c+1]);
                *(float2*)(out + (size_t)r_lo*DIMC + c) = lo;
                *(float2*)(out + (size_t)r_hi*DIMC + c) = hi;
            }
        }
    }
}

// ---------------------------------------------------------------------------
// Per-head LayerNorm + RoPE (in place).  One warp per 64-elem head row.
// ---------------------------------------------------------------------------
__global__ __launch_bounds__(256) void ln_rope(
    int which,
    const float* __restrict__ nw, const float* __restrict__ nb,
    const float* __restrict__ cosb, const float* __restrict__ sinb)
{
    int warp = (blockIdx.x * blockDim.x + threadIdx.x) >> 5;
    int lane = threadIdx.x & 31;
    int bz = warp / (HH*NN);
    int n  = warp & (NN-1);

    float* row = (which ? g_k : g_q) + (size_t)warp * HD;
    float x1 = row[lane], x2 = row[lane + 32];
    float sum = x1 + x2;
    float sq  = x1*x1 + x2*x2;
    #pragma unroll
    for (int o = 16; o; o >>= 1) {
        sum += __shfl_xor_sync(0xffffffffu, sum, o);
        sq  += __shfl_xor_sync(0xffffffffu, sq,  o);
    }
    float mean = sum * (1.f/64.f);
    float var  = sq  * (1.f/64.f) - mean*mean;
    float inv  = rsqrtf(var + 1e-6f);
    float y1 = (x1 - mean) * inv * nw[lane]      + nb[lane];
    float y2 = (x2 - mean) * inv * nw[lane + 32] + nb[lane + 32];

    size_t rbase = ((size_t)bz*NN + n) * HD;
    float c1 = cosb[rbase + lane],      s1 = sinb[rbase + lane];
    float c2 = cosb[rbase + lane + 32], s2 = sinb[rbase + lane + 32];
    row[lane]      = y1*c1 - y2*s1;
    row[lane + 32] = y2*c2 + y1*s2;
}

// ---------------------------------------------------------------------------
// Flash attention via tf32 mma.sync.  256 threads, 8 warps.
// q-tile = 128 rows (warp w owns rows w*16..w*16+15), k-tile = 64.
// smem strides 72 (bank-conflict-free for all fragment access patterns).
// ---------------------------------------------------------------------------
__global__ __launch_bounds__(256) void attn_mma()
{
    extern __shared__ float sm[];
    float* Qs = sm;                 // [128][72]
    float* Ks = sm + 128*72;        // [64][72]
    float* Vs = Ks + 64*72;         // [64][72]
    float* Ps = Vs + 64*72;         // [128][72]

    const int tid = threadIdx.x, lane = tid & 31, w = tid >> 5;
    const int bh = blockIdx.y;
    const int q0 = blockIdx.x * 128;
    const float* qb = g_q + (size_t)bh * NN * HD;
    const float* kb = g_k + (size_t)bh * NN * HD;
    const float* vb = g_v + (size_t)bh * NN * HD;

    // Stage Q (scaled by HD^-0.5, tf32-rounded)
    #pragma unroll
    for (int i = 0; i < 8; i++) {
        int idx = tid + i*256;          // 0..2047 float4 slots
        int r = idx >> 4, c4 = idx & 15;
        float4 v = *(const float4*)(qb + (size_t)(q0 + r)*HD + c4*4);
        float* p = &Qs[r*72 + c4*4];
        p[0] = tf32r(v.x * 0.125f); p[1] = tf32r(v.y * 0.125f);
        p[2] = tf32r(v.z * 0.125f); p[3] = tf32r(v.w * 0.125f);
    }

    float m_lo = -1e30f, m_hi = -1e30f, l_lo = 0.f, l_hi = 0.f;
    float o[8][4];
    #pragma unroll
    for (int nt = 0; nt < 8; nt++)
        #pragma unroll
        for (int e = 0; e < 4; e++) o[nt][e] = 0.f;

    const int rq = w*16 + (lane >> 2);     // this thread's low row in band
    const int qq = lane & 3;

    for (int kt = 0; kt < NN/64; kt++) {
        const int k0 = kt * 64;
        // Stage K, V (tf32-rounded)
        #pragma unroll
        for (int i = 0; i < 4; i++) {
            int idx = tid + i*256;          // 0..1023
            int r = idx >> 4, c4 = idx & 15;
            float4 kv = *(const float4*)(kb + (size_t)(k0 + r)*HD + c4*4);
            float* pk = &Ks[r*72 + c4*4];
            pk[0] = tf32r(kv.x); pk[1] = tf32r(kv.y);
            pk[2] = tf32r(kv.z); pk[3] = tf32r(kv.w);
            float4 vv = *(const float4*)(vb + (size_t)(k0 + r)*HD + c4*4);
            float* pv = &Vs[r*72 + c4*4];
            pv[0] = tf32r(vv.x); pv[1] = tf32r(vv.y);
            pv[2] = tf32r(vv.z); pv[3] = tf32r(vv.w);
        }
        __syncthreads();

        // S = Q @ K^T   (warp: 16 rows x 64 keys)
        float s[8][4];
        #pragma unroll
        for (int nt = 0; nt < 8; nt++)
            #pragma unroll
            for (int e = 0; e < 4; e++) s[nt][e] = 0.f;
        #pragma unroll
        for (int ks = 0; ks < 8; ks++) {
            const int kk = ks * 8;
            float a0 = Qs[rq*72     + kk + qq];
            float a1 = Qs[(rq+8)*72 + kk + qq];
            float a2 = Qs[rq*72     + kk + qq + 4];
            float a3 = Qs[(rq+8)*72 + kk + qq + 4];
            #pragma unroll
            for (int nt = 0; nt < 8; nt++) {
                int cn = nt*8 + (lane >> 2);
                float b0 = Ks[cn*72 + kk + qq];
                float b1 = Ks[cn*72 + kk + qq + 4];
                MMA_TF32(s[nt], a0, a1, a2, a3, b0, b1);
            }
        }

        // Online softmax (rows lane/4 and lane/4+8 of the warp band)
        float tm_lo = -1e30f, tm_hi = -1e30f;
        #pragma unroll
        for (int nt = 0; nt < 8; nt++) {
            tm_lo = fmaxf(tm_lo, fmaxf(s[nt][0], s[nt][1]));
            tm_hi = fmaxf(tm_hi, fmaxf(s[nt][2], s[nt][3]));
        }
        #pragma unroll
        for (int off = 1; off <= 2; off <<= 1) {
            tm_lo = fmaxf(tm_lo, __shfl_xor_sync(0xffffffffu, tm_lo, off));
            tm_hi = fmaxf(tm_hi, __shfl_xor_sync(0xffffffffu, tm_hi, off));
        }
        float mn_lo = fmaxf(m_lo, tm_lo), mn_hi = fmaxf(m_hi, tm_hi);
        float al_lo = __expf(m_lo - mn_lo), al_hi = __expf(m_hi - mn_hi);
        m_lo = mn_lo; m_hi = mn_hi;
        float rs_lo = 0.f, rs_hi = 0.f;
        #pragma unroll
        for (int nt = 0; nt < 8; nt++) {
            s[nt][0] = __expf(s[nt][0] - m_lo);
            s[nt][1] = __expf(s[nt][1] - m_lo);
            s[nt][2] = __expf(s[nt][2] - m_hi);
            s[nt][3] = __expf(s[nt][3] - m_hi);
            rs_lo += s[nt][0] + s[nt][1];
            rs_hi += s[nt][2] + s[nt][3];
        }
        #pragma unroll
        for (int off = 1; off <= 2; off <<= 1) {
            rs_lo += __shfl_xor_sync(0xffffffffu, rs_lo, off);
            rs_hi += __shfl_xor_sync(0xffffffffu, rs_hi, off);
        }
        l_lo = l_lo * al_lo + rs_lo;
        l_hi = l_hi * al_hi + rs_hi;
        #pragma unroll
        for (int nt = 0; nt < 8; nt++) {
            o[nt][0] *= al_lo; o[nt][1] *= al_lo;
            o[nt][2] *= al_hi; o[nt][3] *= al_hi;
        }

        // Stage P (tf32) — warp-local rows only
        {
            int cp = (lane & 3) * 2;
            #pragma unroll
            for (int nt = 0; nt < 8; nt++) {
                *(float2*)&Ps[rq*72     + nt*8 + cp] =
                    make_float2(tf32r(s[nt][0]), tf32r(s[nt][1]));
                *(float2*)&Ps[(rq+8)*72 + nt*8 + cp] =
                    make_float2(tf32r(s[nt][2]), tf32r(s[nt][3]));
            }
        }
        __syncwarp();

        // O += P @ V   (keys = inner dim)
        #pragma unroll
        for (int ks = 0; ks < 8; ks++) {
            const int kk = ks * 8;
            float a0 = Ps[rq*72     + kk + qq];
            float a1 = Ps[(rq+8)*72 + kk + qq];
            float a2 = Ps[rq*72     + kk + qq + 4];
            float a3 = Ps[(rq+8)*72 + kk + qq + 4];
            #pragma unroll
            for (int nt = 0; nt < 8; nt++) {
                int nv = nt*8 + (lane >> 2);
                float b0 = Vs[(kk + qq)*72     + nv];
                float b1 = Vs[(kk + qq + 4)*72 + nv];
                MMA_TF32(o[nt], a0, a1, a2, a3, b0, b1);
            }
        }
        __syncthreads();   // protect Ks/Vs before next tile's staging
    }

    // Finalize
    float inv_lo = 1.f / l_lo, inv_hi = 1.f / l_hi;
    int r_lo = q0 + w*16 + (lane >> 2);
    int r_hi = r_lo + 8;
    #pragma unroll
    for (int nt = 0; nt < 8; nt++) {
        int c = nt*8 + (lane & 3)*2;
        *(float2*)(g_o + ((size_t)bh*NN + r_lo)*HD + c) =
            make_float2(o[nt][0]*inv_lo, o[nt][1]*inv_lo);
        *(float2*)(g_o + ((size_t)bh*NN + r_hi)*HD + c) =
            make_float2(o[nt][2]*inv_hi, o[nt][3]*inv_hi);
    }
}

// ---------------------------------------------------------------------------
extern "C" void kernel_launch(void* const* d_in, const int* in_sizes, int n_in,
                              void* d_out, int out_size)
{
    const float* x   = (const float*)d_in[0];
    const float* rc  = (const float*)d_in[1];
    const float* rs  = (const float*)d_in[2];
    const float* Wq  = (const float*)d_in[3];
    const float* bq  = (const float*)d_in[4];
    const float* Wk  = (const float*)d_in[5];
    const float* bk  = (const float*)d_in[6];
    const float* Wv  = (const float*)d_in[7];
    const float* bv  = (const float*)d_in[8];
    const float* qnw = (const float*)d_in[9];
    const float* qnb = (const float*)d_in[10];
    const float* knw = (const float*)d_in[11];
    const float* knb = (const float*)d_in[12];
    const float* Wo  = (const float*)d_in[13];
    const float* bo  = (const float*)d_in[14];
    float* out = (float*)d_out;

    const int attn_smem = (128 + 64 + 64 + 128) * 72 * (int)sizeof(float); // 110592
    cudaFuncSetAttribute(attn_mma,
                         cudaFuncAttributeMaxDynamicSharedMemorySize, attn_smem);

    float* d_wt;  cudaGetSymbolAddress((void**)&d_wt,  g_wt);
    float* d_wot; cudaGetSymbolAddress((void**)&d_wot, g_wo_t);

    tr_w<<<dim3(32, 32), 256>>>(Wq, d_wt);
    tr_w<<<dim3(32, 32), 256>>>(Wk, d_wt + DIMC*DIMC);
    tr_w<<<dim3(32, 32), 256>>>(Wv, d_wt + 2*DIMC*DIMC);
    tr_w<<<dim3(32, 32), 256>>>(Wo, d_wot);

    mm_mma<<<dim3(24, 32), 256>>>(0, x, bq, bk, bv, bo, out);

    const int rows = BB*HH*NN;
    ln_rope<<<rows/8, 256>>>(0, qnw, qnb, rc, rs);
    ln_rope<<<rows/8, 256>>>(1, knw, knb, rc, rs);

    attn_mma<<<dim3(NN/128, BB*HH), 256, attn_smem>>>();

    mm_mma<<<dim3(8, 32), 256>>>(1, x, bq, bk, bv, bo, out);
}

// round 7
// speedup vs baseline: 2.8125x; 1.6938x over previous
#include <cuda_runtime.h>
#include <cstdint>

#define BB   2
#define NN   2048
#define DIMC 1024
#define HH   16
#define HD   64

// Scratch (allocation-free requirement)
__device__ float g_q[BB*HH*NN*HD];
__device__ float g_k[BB*HH*NN*HD];
__device__ float g_v[BB*HH*NN*HD];
__device__ float g_o[BB*HH*NN*HD];
__device__ float g_wt[3*DIMC*DIMC];    // transposed [Wq|Wk|Wv]
__device__ float g_wo_t[DIMC*DIMC];    // transposed Wo

// ---------------------------------------------------------------------------
__device__ __forceinline__ float tf32r(float x) {
    uint32_t u;
    asm("cvt.rna.tf32.f32 %0, %1;" : "=r"(u) : "f"(x));
    return __uint_as_float(u);
}

#define MMA_TF32(c, a0, a1, a2, a3, b0, b1)                                   \
    asm volatile(                                                             \
        "mma.sync.aligned.m16n8k8.row.col.f32.tf32.tf32.f32 "                 \
        "{%0,%1,%2,%3}, {%4,%5,%6,%7}, {%8,%9}, {%0,%1,%2,%3};"               \
        : "+f"((c)[0]), "+f"((c)[1]), "+f"((c)[2]), "+f"((c)[3])              \
        : "r"(__float_as_uint(a0)), "r"(__float_as_uint(a1)),                 \
          "r"(__float_as_uint(a2)), "r"(__float_as_uint(a3)),                 \
          "r"(__float_as_uint(b0)), "r"(__float_as_uint(b1)))

// ---------------------------------------------------------------------------
// Weight transpose: dst[c][k] = src[k][c], 1024x1024.
// ---------------------------------------------------------------------------
__global__ __launch_bounds__(256) void tr_w(const float* __restrict__ src,
                                            float* __restrict__ dst)
{
    __shared__ float t[32][33];
    int tx = threadIdx.x & 31, ty = threadIdx.x >> 5;
    int cb = blockIdx.x * 32, kb = blockIdx.y * 32;
    #pragma unroll
    for (int r = 0; r < 4; r++)
        t[ty + 8*r][tx] = src[(size_t)(kb + ty + 8*r)*DIMC + cb + tx];
    __syncthreads();
    #pragma unroll
    for (int r = 0; r < 4; r++)
        dst[(size_t)(cb + ty + 8*r)*DIMC + kb + tx] = t[tx][ty + 8*r];
}

// ---------------------------------------------------------------------------
// tf32 mma.sync GEMM: 128x128 tile, K=1024.  8 warps (4 m x 2 n),
// warp tile 32x64 = 2 mtiles x 8 ntiles of m16n8k8.
// mode 0: A = x, B = g_wt (3072 rows), scatter epilogue -> g_q/g_k/g_v
// mode 1: A = gathered g_o, B = g_wo_t, epilogue -> out (+bo)
// ---------------------------------------------------------------------------
__global__ __launch_bounds__(256) void mm_mma(
    int mode,
    const float* __restrict__ x,
    const float* __restrict__ bq, const float* __restrict__ bk,
    const float* __restrict__ bv, const float* __restrict__ bo,
    float* __restrict__ out)
{
    __shared__ float As[128*36];
    __shared__ float Bs[128*36];
    const int tid = threadIdx.x, lane = tid & 31, w = tid >> 5;
    const int wm = w & 3, wn = w >> 2;
    const int m0 = blockIdx.y * 128, c0 = blockIdx.x * 128;
    const float* Bsrc = (mode == 0) ? g_wt : g_wo_t;

    float acc[2][8][4];
    #pragma unroll
    for (int mt = 0; mt < 2; mt++)
        #pragma unroll
        for (int nt = 0; nt < 8; nt++)
            #pragma unroll
            for (int e = 0; e < 4; e++) acc[mt][nt][e] = 0.f;

    for (int kc = 0; kc < DIMC/32; kc++) {
        const int k0 = kc * 32;
        #pragma unroll
        for (int i = 0; i < 4; i++) {
            int idx = tid + i*256;          // 0..1023 float4 slots
            int r = idx >> 3, c4 = idx & 7;
            float4 a;
            if (mode == 0) {
                a = *(const float4*)(x + (size_t)(m0 + r)*DIMC + k0 + c4*4);
            } else {
                int m = m0 + r, bz = m >> 11, n = m & (NN-1);
                int k = k0 + c4*4, h = k >> 6, d = k & 63;
                a = *(const float4*)(g_o + (((size_t)bz*HH + h)*NN + n)*HD + d);
            }
            float* pa = &As[r*36 + c4*4];
            pa[0] = tf32r(a.x); pa[1] = tf32r(a.y);
            pa[2] = tf32r(a.z); pa[3] = tf32r(a.w);
            float4 wv = *(const float4*)(Bsrc + (size_t)(c0 + r)*DIMC + k0 + c4*4);
            float* pb = &Bs[r*36 + c4*4];
            pb[0] = tf32r(wv.x); pb[1] = tf32r(wv.y);
            pb[2] = tf32r(wv.z); pb[3] = tf32r(wv.w);
        }
        __syncthreads();
        #pragma unroll
        for (int ks = 0; ks < 4; ks++) {
            const int kk = ks * 8;
            float a[2][4];
            #pragma unroll
            for (int mt = 0; mt < 2; mt++) {
                int rm = wm*32 + mt*16 + (lane >> 2);
                a[mt][0] = As[rm*36      + kk + (lane & 3)];
                a[mt][1] = As[(rm+8)*36  + kk + (lane & 3)];
                a[mt][2] = As[rm*36      + kk + (lane & 3) + 4];
                a[mt][3] = As[(rm+8)*36  + kk + (lane & 3) + 4];
            }
            #pragma unroll
            for (int nt = 0; nt < 8; nt++) {
                int cn = wn*64 + nt*8 + (lane >> 2);
                float b0 = Bs[cn*36 + kk + (lane & 3)];
                float b1 = Bs[cn*36 + kk + (lane & 3) + 4];
                MMA_TF32(acc[0][nt], a[0][0], a[0][1], a[0][2], a[0][3], b0, b1);
                MMA_TF32(acc[1][nt], a[1][0], a[1][1], a[1][2], a[1][3], b0, b1);
            }
        }
        __syncthreads();
    }

    // Epilogue
    #pragma unroll
    for (int mt = 0; mt < 2; mt++) {
        int r_lo = m0 + wm*32 + mt*16 + (lane >> 2);
        int r_hi = r_lo + 8;
        #pragma unroll
        for (int nt = 0; nt < 8; nt++) {
            int c = c0 + wn*64 + nt*8 + (lane & 3)*2;
            if (mode == 0) {
                #pragma unroll
                for (int e = 0; e < 4; e++) {
                    int cc = c + (e & 1);
                    int m  = (e < 2) ? r_lo : r_hi;
                    int bz = m >> 11, n = m & (NN-1);
                    float bias = (cc < DIMC) ? bq[cc]
                               : (cc < 2*DIMC) ? bk[cc - DIMC] : bv[cc - 2*DIMC];
                    float v = acc[mt][nt][e] + bias;
                    int h = cc / 192, t = cc % 192, d = t & 63;
                    float* dst = (t < 64) ? g_q : (t < 128) ? g_k : g_v;
                    dst[(((size_t)bz*HH + h)*NN + n)*HD + d] = v;
                }
            } else {
                float2 lo = make_float2(acc[mt][nt][0] + bo[c],
                                        acc[mt][nt][1] + bo[c+1]);
                float2 hi = make_float2(acc[mt][nt][2] + bo[c],
                                        acc[mt][nt][3] + bo[c+1]);
                *(float2*)(out + (size_t)r_lo*DIMC + c) = lo;
                *(float2*)(out + (size_t)r_hi*DIMC + c) = hi;
            }
        }
    }
}

// ---------------------------------------------------------------------------
// Per-head LayerNorm + RoPE (in place).  One warp per 64-elem head row.
// ---------------------------------------------------------------------------
__global__ __launch_bounds__(256) void ln_rope(
    int which,
    const float* __restrict__ nw, const float* __restrict__ nb,
    const float* __restrict__ cosb, const float* __restrict__ sinb)
{
    int warp = (blockIdx.x * blockDim.x + threadIdx.x) >> 5;
    int lane = threadIdx.x & 31;
    int bz = warp / (HH*NN);
    int n  = warp & (NN-1);

    float* row = (which ? g_k : g_q) + (size_t)warp * HD;
    float x1 = row[lane], x2 = row[lane + 32];
    float sum = x1 + x2;
    float sq  = x1*x1 + x2*x2;
    #pragma unroll
    for (int o = 16; o; o >>= 1) {
        sum += __shfl_xor_sync(0xffffffffu, sum, o);
        sq  += __shfl_xor_sync(0xffffffffu, sq,  o);
    }
    float mean = sum * (1.f/64.f);
    float var  = sq  * (1.f/64.f) - mean*mean;
    float inv  = rsqrtf(var + 1e-6f);
    float y1 = (x1 - mean) * inv * nw[lane]      + nb[lane];
    float y2 = (x2 - mean) * inv * nw[lane + 32] + nb[lane + 32];

    size_t rbase = ((size_t)bz*NN + n) * HD;
    float c1 = cosb[rbase + lane],      s1 = sinb[rbase + lane];
    float c2 = cosb[rbase + lane + 32], s2 = sinb[rbase + lane + 32];
    row[lane]      = y1*c1 - y2*s1;
    row[lane + 32] = y2*c2 + y1*s2;
}

// ---------------------------------------------------------------------------
// Flash attention via tf32 mma.sync, v2.
// 128 threads / 4 warps; q-tile 128 rows (warp owns 32 rows = 2 mtiles);
// k-tile 64.  Q fragments live in registers (loaded once from gmem).
// Smem strides: Ks/Ps 68 (conflict-free for lane>>2-indexed rows),
// Vs 72 (conflict-free for qq-indexed rows).
// ---------------------------------------------------------------------------
__global__ __launch_bounds__(128) void attn_mma()
{
    extern __shared__ float sm[];
    float* Ks = sm;                 // [64][68]
    float* Vs = sm + 64*68;         // [64][72]
    float* Ps = Vs + 64*72;         // [128][68]

    const int tid = threadIdx.x, lane = tid & 31, w = tid >> 5;   // w: 0..3
    const int bh = blockIdx.y;
    const int q0 = blockIdx.x * 128;
    const float* qb = g_q + (size_t)bh * NN * HD;
    const float* kb = g_k + (size_t)bh * NN * HD;
    const float* vb = g_v + (size_t)bh * NN * HD;

    const int rr = lane >> 2;       // 0..7
    const int qq = lane & 3;

    // Q fragments in registers (scaled by HD^-0.5, tf32-rounded)
    float qf[2][8][4];
    #pragma unroll
    for (int mt = 0; mt < 2; mt++) {
        int rbase = q0 + w*32 + mt*16 + rr;
        #pragma unroll
        for (int ks = 0; ks < 8; ks++) {
            int c = ks*8 + qq;
            qf[mt][ks][0] = tf32r(qb[(size_t)rbase*HD     + c    ] * 0.125f);
            qf[mt][ks][1] = tf32r(qb[(size_t)(rbase+8)*HD + c    ] * 0.125f);
            qf[mt][ks][2] = tf32r(qb[(size_t)rbase*HD     + c + 4] * 0.125f);
            qf[mt][ks][3] = tf32r(qb[(size_t)(rbase+8)*HD + c + 4] * 0.125f);
        }
    }

    float m_i[2][2], l_i[2][2];     // [mt][lo/hi]
    float o[2][8][4];
    #pragma unroll
    for (int mt = 0; mt < 2; mt++) {
        m_i[mt][0] = -1e30f; m_i[mt][1] = -1e30f;
        l_i[mt][0] = 0.f;    l_i[mt][1] = 0.f;
        #pragma unroll
        for (int nt = 0; nt < 8; nt++)
            #pragma unroll
            for (int e = 0; e < 4; e++) o[mt][nt][e] = 0.f;
    }

    for (int kt = 0; kt < NN/64; kt++) {
        const int k0 = kt * 64;
        // Stage K (stride 68) and V (stride 72), tf32-rounded
        #pragma unroll
        for (int i = 0; i < 8; i++) {
            int idx = tid + i*128;          // 0..1023
            int r = idx >> 4, c4 = idx & 15;
            float4 kv = *(const float4*)(kb + (size_t)(k0 + r)*HD + c4*4);
            float* pk = &Ks[r*68 + c4*4];
            pk[0] = tf32r(kv.x); pk[1] = tf32r(kv.y);
            pk[2] = tf32r(kv.z); pk[3] = tf32r(kv.w);
            float4 vv = *(const float4*)(vb + (size_t)(k0 + r)*HD + c4*4);
            float* pv = &Vs[r*72 + c4*4];
            pv[0] = tf32r(vv.x); pv[1] = tf32r(vv.y);
            pv[2] = tf32r(vv.z); pv[3] = tf32r(vv.w);
        }
        __syncthreads();

        // Per-mtile: S = Q K^T, online softmax, stage P
        #pragma unroll
        for (int mt = 0; mt < 2; mt++) {
            float s[8][4];
            #pragma unroll
            for (int nt = 0; nt < 8; nt++)
                #pragma unroll
                for (int e = 0; e < 4; e++) s[nt][e] = 0.f;
            #pragma unroll
            for (int ks = 0; ks < 8; ks++) {
                const int kk = ks * 8;
                float a0 = qf[mt][ks][0], a1 = qf[mt][ks][1];
                float a2 = qf[mt][ks][2], a3 = qf[mt][ks][3];
                #pragma unroll
                for (int nt = 0; nt < 8; nt++) {
                    int cn = nt*8 + rr;
                    float b0 = Ks[cn*68 + kk + qq];
                    float b1 = Ks[cn*68 + kk + qq + 4];
                    MMA_TF32(s[nt], a0, a1, a2, a3, b0, b1);
                }
            }

            // Online softmax (rows rr and rr+8 of this mtile)
            float tm_lo = -1e30f, tm_hi = -1e30f;
            #pragma unroll
            for (int nt = 0; nt < 8; nt++) {
                tm_lo = fmaxf(tm_lo, fmaxf(s[nt][0], s[nt][1]));
                tm_hi = fmaxf(tm_hi, fmaxf(s[nt][2], s[nt][3]));
            }
            #pragma unroll
            for (int off = 1; off <= 2; off <<= 1) {
                tm_lo = fmaxf(tm_lo, __shfl_xor_sync(0xffffffffu, tm_lo, off));
                tm_hi = fmaxf(tm_hi, __shfl_xor_sync(0xffffffffu, tm_hi, off));
            }
            float mn_lo = fmaxf(m_i[mt][0], tm_lo);
            float mn_hi = fmaxf(m_i[mt][1], tm_hi);
            float al_lo = __expf(m_i[mt][0] - mn_lo);
            float al_hi = __expf(m_i[mt][1] - mn_hi);
            m_i[mt][0] = mn_lo; m_i[mt][1] = mn_hi;
            float rs_lo = 0.f, rs_hi = 0.f;
            #pragma unroll
            for (int nt = 0; nt < 8; nt++) {
                s[nt][0] = __expf(s[nt][0] - mn_lo);
                s[nt][1] = __expf(s[nt][1] - mn_lo);
                s[nt][2] = __expf(s[nt][2] - mn_hi);
                s[nt][3] = __expf(s[nt][3] - mn_hi);
                rs_lo += s[nt][0] + s[nt][1];
                rs_hi += s[nt][2] + s[nt][3];
            }
            #pragma unroll
            for (int off = 1; off <= 2; off <<= 1) {
                rs_lo += __shfl_xor_sync(0xffffffffu, rs_lo, off);
                rs_hi += __shfl_xor_sync(0xffffffffu, rs_hi, off);
            }
            l_i[mt][0] = l_i[mt][0] * al_lo + rs_lo;
            l_i[mt][1] = l_i[mt][1] * al_hi + rs_hi;
            #pragma unroll
            for (int nt = 0; nt < 8; nt++) {
                o[mt][nt][0] *= al_lo; o[mt][nt][1] *= al_lo;
                o[mt][nt][2] *= al_hi; o[mt][nt][3] *= al_hi;
            }

            // Stage P (tf32) into this warp's rows of Ps
            int prow = w*32 + mt*16 + rr;
            int cp = qq * 2;
            #pragma unroll
            for (int nt = 0; nt < 8; nt++) {
                *(float2*)&Ps[prow*68     + nt*8 + cp] =
                    make_float2(tf32r(s[nt][0]), tf32r(s[nt][1]));
                *(float2*)&Ps[(prow+8)*68 + nt*8 + cp] =
                    make_float2(tf32r(s[nt][2]), tf32r(s[nt][3]));
            }
        }
        __syncwarp();

        // O += P @ V  (V B-frags loaded once, used for both mtiles)
        #pragma unroll
        for (int ks = 0; ks < 8; ks++) {
            const int kk = ks * 8;
            float pa[2][4];
            #pragma unroll
            for (int mt = 0; mt < 2; mt++) {
                int prow = w*32 + mt*16 + rr;
                pa[mt][0] = Ps[prow*68     + kk + qq];
                pa[mt][1] = Ps[(prow+8)*68 + kk + qq];
                pa[mt][2] = Ps[prow*68     + kk + qq + 4];
                pa[mt][3] = Ps[(prow+8)*68 + kk + qq + 4];
            }
            #pragma unroll
            for (int nt = 0; nt < 8; nt++) {
                int nv = nt*8 + rr;
                float b0 = Vs[(kk + qq)*72     + nv];
                float b1 = Vs[(kk + qq + 4)*72 + nv];
                MMA_TF32(o[0][nt], pa[0][0], pa[0][1], pa[0][2], pa[0][3], b0, b1);
                MMA_TF32(o[1][nt], pa[1][0], pa[1][1], pa[1][2], pa[1][3], b0, b1);
            }
        }
        __syncthreads();   // protect Ks/Vs before next tile's staging
    }

    // Finalize
    #pragma unroll
    for (int mt = 0; mt < 2; mt++) {
        float inv_lo = 1.f / l_i[mt][0], inv_hi = 1.f / l_i[mt][1];
        int r_lo = q0 + w*32 + mt*16 + rr;
        int r_hi = r_lo + 8;
        #pragma unroll
        for (int nt = 0; nt < 8; nt++) {
            int c = nt*8 + qq*2;
            *(float2*)(g_o + ((size_t)bh*NN + r_lo)*HD + c) =
                make_float2(o[mt][nt][0]*inv_lo, o[mt][nt][1]*inv_lo);
            *(float2*)(g_o + ((size_t)bh*NN + r_hi)*HD + c) =
                make_float2(o[mt][nt][2]*inv_hi, o[mt][nt][3]*inv_hi);
        }
    }
}

// ---------------------------------------------------------------------------
extern "C" void kernel_launch(void* const* d_in, const int* in_sizes, int n_in,
                              void* d_out, int out_size)
{
    const float* x   = (const float*)d_in[0];
    const float* rc  = (const float*)d_in[1];
    const float* rs  = (const float*)d_in[2];
    const float* Wq  = (const float*)d_in[3];
    const float* bq  = (const float*)d_in[4];
    const float* Wk  = (const float*)d_in[5];
    const float* bk  = (const float*)d_in[6];
    const float* Wv  = (const float*)d_in[7];
    const float* bv  = (const float*)d_in[8];
    const float* qnw = (const float*)d_in[9];
    const float* qnb = (const float*)d_in[10];
    const float* knw = (const float*)d_in[11];
    const float* knb = (const float*)d_in[12];
    const float* Wo  = (const float*)d_in[13];
    const float* bo  = (const float*)d_in[14];
    float* out = (float*)d_out;

    const int attn_smem = (64*68 + 64*72 + 128*68) * (int)sizeof(float); // 70656
    cudaFuncSetAttribute(attn_mma,
                         cudaFuncAttributeMaxDynamicSharedMemorySize, attn_smem);

    float* d_wt;  cudaGetSymbolAddress((void**)&d_wt,  g_wt);
    float* d_wot; cudaGetSymbolAddress((void**)&d_wot, g_wo_t);

    tr_w<<<dim3(32, 32), 256>>>(Wq, d_wt);
    tr_w<<<dim3(32, 32), 256>>>(Wk, d_wt + DIMC*DIMC);
    tr_w<<<dim3(32, 32), 256>>>(Wv, d_wt + 2*DIMC*DIMC);
    tr_w<<<dim3(32, 32), 256>>>(Wo, d_wot);

    mm_mma<<<dim3(24, 32), 256>>>(0, x, bq, bk, bv, bo, out);

    const int rows = BB*HH*NN;
    ln_rope<<<rows/8, 256>>>(0, qnw, qnb, rc, rs);
    ln_rope<<<rows/8, 256>>>(1, knw, knb, rc, rs);

    attn_mma<<<dim3(NN/128, BB*HH), 128, attn_smem>>>();

    mm_mma<<<dim3(8, 32), 256>>>(1, x, bq, bk, bv, bo, out);
}

// round 8
// speedup vs baseline: 3.0065x; 1.0690x over previous
#include <cuda_runtime.h>
#include <cstdint>

#define BB   2
#define NN   2048
#define DIMC 1024
#define HH   16
#define HD   64

// Scratch (allocation-free requirement)
__device__ float g_q[BB*HH*NN*HD];
__device__ float g_k[BB*HH*NN*HD];
__device__ float g_v[BB*HH*NN*HD];
__device__ float g_o[BB*HH*NN*HD];
__device__ float g_wt[3*DIMC*DIMC];    // transposed [Wq|Wk|Wv]
__device__ float g_wo_t[DIMC*DIMC];    // transposed Wo

// ---------------------------------------------------------------------------
__device__ __forceinline__ float tf32r(float x) {
    uint32_t u;
    asm("cvt.rna.tf32.f32 %0, %1;" : "=r"(u) : "f"(x));
    return __uint_as_float(u);
}

#define MMA_TF32(c, a0, a1, a2, a3, b0, b1)                                   \
    asm volatile(                                                             \
        "mma.sync.aligned.m16n8k8.row.col.f32.tf32.tf32.f32 "                 \
        "{%0,%1,%2,%3}, {%4,%5,%6,%7}, {%8,%9}, {%0,%1,%2,%3};"               \
        : "+f"((c)[0]), "+f"((c)[1]), "+f"((c)[2]), "+f"((c)[3])              \
        : "r"(__float_as_uint(a0)), "r"(__float_as_uint(a1)),                 \
          "r"(__float_as_uint(a2)), "r"(__float_as_uint(a3)),                 \
          "r"(__float_as_uint(b0)), "r"(__float_as_uint(b1)))

// ---------------------------------------------------------------------------
// Weight transpose: dst[c][k] = src[k][c], 1024x1024.
// ---------------------------------------------------------------------------
__global__ __launch_bounds__(256) void tr_w(const float* __restrict__ src,
                                            float* __restrict__ dst)
{
    __shared__ float t[32][33];
    int tx = threadIdx.x & 31, ty = threadIdx.x >> 5;
    int cb = blockIdx.x * 32, kb = blockIdx.y * 32;
    #pragma unroll
    for (int r = 0; r < 4; r++)
        t[ty + 8*r][tx] = src[(size_t)(kb + ty + 8*r)*DIMC + cb + tx];
    __syncthreads();
    #pragma unroll
    for (int r = 0; r < 4; r++)
        dst[(size_t)(cb + ty + 8*r)*DIMC + kb + tx] = t[tx][ty + 8*r];
}

// ---------------------------------------------------------------------------
// tf32 mma.sync GEMM, double-buffered software pipeline.
// 128x128 tile, K=1024 in 32 chunks of 32.  8 warps (4 m x 2 n),
// warp tile 32x64 = 2 mtiles x 8 ntiles of m16n8k8.
// Chunk kc: prefetch kc+1 from gmem into regs, compute on smem buf kc&1,
// store prefetch (tf32-rounded) to buf (kc+1)&1, one __syncthreads.
// mode 0: A = x, B = g_wt (3072 rows), scatter epilogue -> g_q/g_k/g_v
// mode 1: A = gathered g_o, B = g_wo_t, epilogue -> out (+bo)
// ---------------------------------------------------------------------------
#define MMS (128*36)

__global__ __launch_bounds__(256) void mm_mma(
    int mode,
    const float* __restrict__ x,
    const float* __restrict__ bq, const float* __restrict__ bk,
    const float* __restrict__ bv, const float* __restrict__ bo,
    float* __restrict__ out)
{
    extern __shared__ float dsm[];
    float* As = dsm;            // [2][128*36]
    float* Bs = dsm + 2*MMS;    // [2][128*36]

    const int tid = threadIdx.x, lane = tid & 31, w = tid >> 5;
    const int wm = w & 3, wn = w >> 2;
    const int m0 = blockIdx.y * 128, c0 = blockIdx.x * 128;
    const float* Bsrc = (mode == 0) ? g_wt : g_wo_t;

    // Per-thread fixed (row, col4) slots for staging
    int rA[4], cA[4];
    #pragma unroll
    for (int i = 0; i < 4; i++) {
        int idx = tid + i*256;          // 0..1023 float4 slots
        rA[i] = idx >> 3; cA[i] = idx & 7;
    }

    float acc[2][8][4];
    #pragma unroll
    for (int mt = 0; mt < 2; mt++)
        #pragma unroll
        for (int nt = 0; nt < 8; nt++)
            #pragma unroll
            for (int e = 0; e < 4; e++) acc[mt][nt][e] = 0.f;

    float4 pa[4], pb[4];

    // ---- gmem fetch of chunk kc into pa/pb ----
    auto fetch = [&](int kc) {
        const int k0 = kc * 32;
        #pragma unroll
        for (int i = 0; i < 4; i++) {
            int r = rA[i], c4 = cA[i];
            if (mode == 0) {
                pa[i] = *(const float4*)(x + (size_t)(m0 + r)*DIMC + k0 + c4*4);
            } else {
                int m = m0 + r, bz = m >> 11, n = m & (NN-1);
                int k = k0 + c4*4, h = k >> 6, d = k & 63;
                pa[i] = *(const float4*)(g_o + (((size_t)bz*HH + h)*NN + n)*HD + d);
            }
            pb[i] = *(const float4*)(Bsrc + (size_t)(c0 + r)*DIMC + k0 + c4*4);
        }
    };
    // ---- store pa/pb (tf32-rounded) into smem buffer b ----
    auto stage = [&](int b) {
        #pragma unroll
        for (int i = 0; i < 4; i++) {
            float* qa = &As[b*MMS + rA[i]*36 + cA[i]*4];
            qa[0] = tf32r(pa[i].x); qa[1] = tf32r(pa[i].y);
            qa[2] = tf32r(pa[i].z); qa[3] = tf32r(pa[i].w);
            float* qb = &Bs[b*MMS + rA[i]*36 + cA[i]*4];
            qb[0] = tf32r(pb[i].x); qb[1] = tf32r(pb[i].y);
            qb[2] = tf32r(pb[i].z); qb[3] = tf32r(pb[i].w);
        }
    };

    fetch(0);
    stage(0);
    __syncthreads();

    for (int kc = 0; kc < DIMC/32; kc++) {
        const int cur = kc & 1;
        if (kc + 1 < DIMC/32) fetch(kc + 1);

        const float* Ac = &As[cur*MMS];
        const float* Bc = &Bs[cur*MMS];
        #pragma unroll
        for (int ks = 0; ks < 4; ks++) {
            const int kk = ks * 8;
            float a[2][4];
            #pragma unroll
            for (int mt = 0; mt < 2; mt++) {
                int rm = wm*32 + mt*16 + (lane >> 2);
                a[mt][0] = Ac[rm*36      + kk + (lane & 3)];
                a[mt][1] = Ac[(rm+8)*36  + kk + (lane & 3)];
                a[mt][2] = Ac[rm*36      + kk + (lane & 3) + 4];
                a[mt][3] = Ac[(rm+8)*36  + kk + (lane & 3) + 4];
            }
            #pragma unroll
            for (int nt = 0; nt < 8; nt++) {
                int cn = wn*64 + nt*8 + (lane >> 2);
                float b0 = Bc[cn*36 + kk + (lane & 3)];
                float b1 = Bc[cn*36 + kk + (lane & 3) + 4];
                MMA_TF32(acc[0][nt], a[0][0], a[0][1], a[0][2], a[0][3], b0, b1);
                MMA_TF32(acc[1][nt], a[1][0], a[1][1], a[1][2], a[1][3], b0, b1);
            }
        }

        if (kc + 1 < DIMC/32) {
            stage(cur ^ 1);
            __syncthreads();
        }
    }

    // Epilogue
    #pragma unroll
    for (int mt = 0; mt < 2; mt++) {
        int r_lo = m0 + wm*32 + mt*16 + (lane >> 2);
        int r_hi = r_lo + 8;
        #pragma unroll
        for (int nt = 0; nt < 8; nt++) {
            int c = c0 + wn*64 + nt*8 + (lane & 3)*2;
            if (mode == 0) {
                #pragma unroll
                for (int e = 0; e < 4; e++) {
                    int cc = c + (e & 1);
                    int m  = (e < 2) ? r_lo : r_hi;
                    int bz = m >> 11, n = m & (NN-1);
                    float bias = (cc < DIMC) ? bq[cc]
                               : (cc < 2*DIMC) ? bk[cc - DIMC] : bv[cc - 2*DIMC];
                    float v = acc[mt][nt][e] + bias;
                    int h = cc / 192, t = cc % 192, d = t & 63;
                    float* dst = (t < 64) ? g_q : (t < 128) ? g_k : g_v;
                    dst[(((size_t)bz*HH + h)*NN + n)*HD + d] = v;
                }
            } else {
                float2 lo = make_float2(acc[mt][nt][0] + bo[c],
                                        acc[mt][nt][1] + bo[c+1]);
                float2 hi = make_float2(acc[mt][nt][2] + bo[c],
                                        acc[mt][nt][3] + bo[c+1]);
                *(float2*)(out + (size_t)r_lo*DIMC + c) = lo;
                *(float2*)(out + (size_t)r_hi*DIMC + c) = hi;
            }
        }
    }
}

// ---------------------------------------------------------------------------
// Per-head LayerNorm + RoPE (in place).  One warp per 64-elem head row.
// ---------------------------------------------------------------------------
__global__ __launch_bounds__(256) void ln_rope(
    int which,
    const float* __restrict__ nw, const float* __restrict__ nb,
    const float* __restrict__ cosb, const float* __restrict__ sinb)
{
    int warp = (blockIdx.x * blockDim.x + threadIdx.x) >> 5;
    int lane = threadIdx.x & 31;
    int bz = warp / (HH*NN);
    int n  = warp & (NN-1);

    float* row = (which ? g_k : g_q) + (size_t)warp * HD;
    float x1 = row[lane], x2 = row[lane + 32];
    float sum = x1 + x2;
    float sq  = x1*x1 + x2*x2;
    #pragma unroll
    for (int o = 16; o; o >>= 1) {
        sum += __shfl_xor_sync(0xffffffffu, sum, o);
        sq  += __shfl_xor_sync(0xffffffffu, sq,  o);
    }
    float mean = sum * (1.f/64.f);
    float var  = sq  * (1.f/64.f) - mean*mean;
    float inv  = rsqrtf(var + 1e-6f);
    float y1 = (x1 - mean) * inv * nw[lane]      + nb[lane];
    float y2 = (x2 - mean) * inv * nw[lane + 32] + nb[lane + 32];

    size_t rbase = ((size_t)bz*NN + n) * HD;
    float c1 = cosb[rbase + lane],      s1 = sinb[rbase + lane];
    float c2 = cosb[rbase + lane + 32], s2 = sinb[rbase + lane + 32];
    row[lane]      = y1*c1 - y2*s1;
    row[lane + 32] = y2*c2 + y1*s2;
}

// ---------------------------------------------------------------------------
// Flash attention via tf32 mma.sync (unchanged, known-good at 694us total).
// 128 threads / 4 warps; q-tile 128 rows; k-tile 64.
// ---------------------------------------------------------------------------
__global__ __launch_bounds__(128) void attn_mma()
{
    extern __shared__ float sm[];
    float* Ks = sm;                 // [64][68]
    float* Vs = sm + 64*68;         // [64][72]
    float* Ps = Vs + 64*72;         // [128][68]

    const int tid = threadIdx.x, lane = tid & 31, w = tid >> 5;   // w: 0..3
    const int bh = blockIdx.y;
    const int q0 = blockIdx.x * 128;
    const float* qb = g_q + (size_t)bh * NN * HD;
    const float* kb = g_k + (size_t)bh * NN * HD;
    const float* vb = g_v + (size_t)bh * NN * HD;

    const int rr = lane >> 2;       // 0..7
    const int qq = lane & 3;

    // Q fragments in registers (scaled by HD^-0.5, tf32-rounded)
    float qf[2][8][4];
    #pragma unroll
    for (int mt = 0; mt < 2; mt++) {
        int rbase = q0 + w*32 + mt*16 + rr;
        #pragma unroll
        for (int ks = 0; ks < 8; ks++) {
            int c = ks*8 + qq;
            qf[mt][ks][0] = tf32r(qb[(size_t)rbase*HD     + c    ] * 0.125f);
            qf[mt][ks][1] = tf32r(qb[(size_t)(rbase+8)*HD + c    ] * 0.125f);
            qf[mt][ks][2] = tf32r(qb[(size_t)rbase*HD     + c + 4] * 0.125f);
            qf[mt][ks][3] = tf32r(qb[(size_t)(rbase+8)*HD + c + 4] * 0.125f);
        }
    }

    float m_i[2][2], l_i[2][2];     // [mt][lo/hi]
    float o[2][8][4];
    #pragma unroll
    for (int mt = 0; mt < 2; mt++) {
        m_i[mt][0] = -1e30f; m_i[mt][1] = -1e30f;
        l_i[mt][0] = 0.f;    l_i[mt][1] = 0.f;
        #pragma unroll
        for (int nt = 0; nt < 8; nt++)
            #pragma unroll
            for (int e = 0; e < 4; e++) o[mt][nt][e] = 0.f;
    }

    for (int kt = 0; kt < NN/64; kt++) {
        const int k0 = kt * 64;
        // Stage K (stride 68) and V (stride 72), tf32-rounded
        #pragma unroll
        for (int i = 0; i < 8; i++) {
            int idx = tid + i*128;          // 0..1023
            int r = idx >> 4, c4 = idx & 15;
            float4 kv = *(const float4*)(kb + (size_t)(k0 + r)*HD + c4*4);
            float* pk = &Ks[r*68 + c4*4];
            pk[0] = tf32r(kv.x); pk[1] = tf32r(kv.y);
            pk[2] = tf32r(kv.z); pk[3] = tf32r(kv.w);
            float4 vv = *(const float4*)(vb + (size_t)(k0 + r)*HD + c4*4);
            float* pv = &Vs[r*72 + c4*4];
            pv[0] = tf32r(vv.x); pv[1] = tf32r(vv.y);
            pv[2] = tf32r(vv.z); pv[3] = tf32r(vv.w);
        }
        __syncthreads();

        // Per-mtile: S = Q K^T, online softmax, stage P
        #pragma unroll
        for (int mt = 0; mt < 2; mt++) {
            float s[8][4];
            #pragma unroll
            for (int nt = 0; nt < 8; nt++)
                #pragma unroll
                for (int e = 0; e < 4; e++) s[nt][e] = 0.f;
            #pragma unroll
            for (int ks = 0; ks < 8; ks++) {
                const int kk = ks * 8;
                float a0 = qf[mt][ks][0], a1 = qf[mt][ks][1];
                float a2 = qf[mt][ks][2], a3 = qf[mt][ks][3];
                #pragma unroll
                for (int nt = 0; nt < 8; nt++) {
                    int cn = nt*8 + rr;
                    float b0 = Ks[cn*68 + kk + qq];
                    float b1 = Ks[cn*68 + kk + qq + 4];
                    MMA_TF32(s[nt], a0, a1, a2, a3, b0, b1);
                }
            }

            // Online softmax (rows rr and rr+8 of this mtile)
            float tm_lo = -1e30f, tm_hi = -1e30f;
            #pragma unroll
            for (int nt = 0; nt < 8; nt++) {
                tm_lo = fmaxf(tm_lo, fmaxf(s[nt][0], s[nt][1]));
                tm_hi = fmaxf(tm_hi, fmaxf(s[nt][2], s[nt][3]));
            }
            #pragma unroll
            for (int off = 1; off <= 2; off <<= 1) {
                tm_lo = fmaxf(tm_lo, __shfl_xor_sync(0xffffffffu, tm_lo, off));
                tm_hi = fmaxf(tm_hi, __shfl_xor_sync(0xffffffffu, tm_hi, off));
            }
            float mn_lo = fmaxf(m_i[mt][0], tm_lo);
            float mn_hi = fmaxf(m_i[mt][1], tm_hi);
            float al_lo = __expf(m_i[mt][0] - mn_lo);
            float al_hi = __expf(m_i[mt][1] - mn_hi);
            m_i[mt][0] = mn_lo; m_i[mt][1] = mn_hi;
            float rs_lo = 0.f, rs_hi = 0.f;
            #pragma unroll
            for (int nt = 0; nt < 8; nt++) {
                s[nt][0] = __expf(s[nt][0] - mn_lo);
                s[nt][1] = __expf(s[nt][1] - mn_lo);
                s[nt][2] = __expf(s[nt][2] - mn_hi);
                s[nt][3] = __expf(s[nt][3] - mn_hi);
                rs_lo += s[nt][0] + s[nt][1];
                rs_hi += s[nt][2] + s[nt][3];
            }
            #pragma unroll
            for (int off = 1; off <= 2; off <<= 1) {
                rs_lo += __shfl_xor_sync(0xffffffffu, rs_lo, off);
                rs_hi += __shfl_xor_sync(0xffffffffu, rs_hi, off);
            }
            l_i[mt][0] = l_i[mt][0] * al_lo + rs_lo;
            l_i[mt][1] = l_i[mt][1] * al_hi + rs_hi;
            #pragma unroll
            for (int nt = 0; nt < 8; nt++) {
                o[mt][nt][0] *= al_lo; o[mt][nt][1] *= al_lo;
                o[mt][nt][2] *= al_hi; o[mt][nt][3] *= al_hi;
            }

            // Stage P (tf32) into this warp's rows of Ps
            int prow = w*32 + mt*16 + rr;
            int cp = qq * 2;
            #pragma unroll
            for (int nt = 0; nt < 8; nt++) {
                *(float2*)&Ps[prow*68     + nt*8 + cp] =
                    make_float2(tf32r(s[nt][0]), tf32r(s[nt][1]));
                *(float2*)&Ps[(prow+8)*68 + nt*8 + cp] =
                    make_float2(tf32r(s[nt][2]), tf32r(s[nt][3]));
            }
        }
        __syncwarp();

        // O += P @ V  (V B-frags loaded once, used for both mtiles)
        #pragma unroll
        for (int ks = 0; ks < 8; ks++) {
            const int kk = ks * 8;
            float pa[2][4];
            #pragma unroll
            for (int mt = 0; mt < 2; mt++) {
                int prow = w*32 + mt*16 + rr;
                pa[mt][0] = Ps[prow*68     + kk + qq];
                pa[mt][1] = Ps[(prow+8)*68 + kk + qq];
                pa[mt][2] = Ps[prow*68     + kk + qq + 4];
                pa[mt][3] = Ps[(prow+8)*68 + kk + qq + 4];
            }
            #pragma unroll
            for (int nt = 0; nt < 8; nt++) {
                int nv = nt*8 + rr;
                float b0 = Vs[(kk + qq)*72     + nv];
                float b1 = Vs[(kk + qq + 4)*72 + nv];
                MMA_TF32(o[0][nt], pa[0][0], pa[0][1], pa[0][2], pa[0][3], b0, b1);
                MMA_TF32(o[1][nt], pa[1][0], pa[1][1], pa[1][2], pa[1][3], b0, b1);
            }
        }
        __syncthreads();   // protect Ks/Vs before next tile's staging
    }

    // Finalize
    #pragma unroll
    for (int mt = 0; mt < 2; mt++) {
        float inv_lo = 1.f / l_i[mt][0], inv_hi = 1.f / l_i[mt][1];
        int r_lo = q0 + w*32 + mt*16 + rr;
        int r_hi = r_lo + 8;
        #pragma unroll
        for (int nt = 0; nt < 8; nt++) {
            int c = nt*8 + qq*2;
            *(float2*)(g_o + ((size_t)bh*NN + r_lo)*HD + c) =
                make_float2(o[mt][nt][0]*inv_lo, o[mt][nt][1]*inv_lo);
            *(float2*)(g_o + ((size_t)bh*NN + r_hi)*HD + c) =
                make_float2(o[mt][nt][2]*inv_hi, o[mt][nt][3]*inv_hi);
        }
    }
}

// ---------------------------------------------------------------------------
extern "C" void kernel_launch(void* const* d_in, const int* in_sizes, int n_in,
                              void* d_out, int out_size)
{
    const float* x   = (const float*)d_in[0];
    const float* rc  = (const float*)d_in[1];
    const float* rs  = (const float*)d_in[2];
    const float* Wq  = (const float*)d_in[3];
    const float* bq  = (const float*)d_in[4];
    const float* Wk  = (const float*)d_in[5];
    const float* bk  = (const float*)d_in[6];
    const float* Wv  = (const float*)d_in[7];
    const float* bv  = (const float*)d_in[8];
    const float* qnw = (const float*)d_in[9];
    const float* qnb = (const float*)d_in[10];
    const float* knw = (const float*)d_in[11];
    const float* knb = (const float*)d_in[12];
    const float* Wo  = (const float*)d_in[13];
    const float* bo  = (const float*)d_in[14];
    float* out = (float*)d_out;

    const int attn_smem = (64*68 + 64*72 + 128*68) * (int)sizeof(float); // 70656
    cudaFuncSetAttribute(attn_mma,
                         cudaFuncAttributeMaxDynamicSharedMemorySize, attn_smem);
    const int mm_smem = 4 * MMS * (int)sizeof(float);                    // 73728
    cudaFuncSetAttribute(mm_mma,
                         cudaFuncAttributeMaxDynamicSharedMemorySize, mm_smem);

    float* d_wt;  cudaGetSymbolAddress((void**)&d_wt,  g_wt);
    float* d_wot; cudaGetSymbolAddress((void**)&d_wot, g_wo_t);

    tr_w<<<dim3(32, 32), 256>>>(Wq, d_wt);
    tr_w<<<dim3(32, 32), 256>>>(Wk, d_wt + DIMC*DIMC);
    tr_w<<<dim3(32, 32), 256>>>(Wv, d_wt + 2*DIMC*DIMC);
    tr_w<<<dim3(32, 32), 256>>>(Wo, d_wot);

    mm_mma<<<dim3(24, 32), 256, mm_smem>>>(0, x, bq, bk, bv, bo, out);

    const int rows = BB*HH*NN;
    ln_rope<<<rows/8, 256>>>(0, qnw, qnb, rc, rs);
    ln_rope<<<rows/8, 256>>>(1, knw, knb, rc, rs);

    attn_mma<<<dim3(NN/128, BB*HH), 128, attn_smem>>>();

    mm_mma<<<dim3(8, 32), 256, mm_smem>>>(1, x, bq, bk, bv, bo, out);
}

// round 9
// speedup vs baseline: 4.0687x; 1.3533x over previous
#include <cuda_runtime.h>
#include <cuda_fp16.h>
#include <cstdint>

#define BB   2
#define NN   2048
#define DIMC 1024
#define HH   16
#define HD   64

// Scratch (allocation-free requirement)
__device__ float g_q[BB*HH*NN*HD];
__device__ float g_k[BB*HH*NN*HD];
__device__ float g_v[BB*HH*NN*HD];
__device__ float g_o[BB*HH*NN*HD];
__device__ float g_wt[3*DIMC*DIMC];    // transposed [Wq|Wk|Wv]
__device__ float g_wo_t[DIMC*DIMC];    // transposed Wo

// ---------------------------------------------------------------------------
__device__ __forceinline__ uint32_t f22u(float a, float b) {
    __half2 h = __floats2half2_rn(a, b);
    return *(uint32_t*)&h;
}

#define MMA_F16(c, a0, a1, a2, a3, b0, b1)                                    \
    asm volatile(                                                             \
        "mma.sync.aligned.m16n8k16.row.col.f32.f16.f16.f32 "                  \
        "{%0,%1,%2,%3}, {%4,%5,%6,%7}, {%8,%9}, {%0,%1,%2,%3};"               \
        : "+f"((c)[0]), "+f"((c)[1]), "+f"((c)[2]), "+f"((c)[3])              \
        : "r"(a0), "r"(a1), "r"(a2), "r"(a3), "r"(b0), "r"(b1))

// ---------------------------------------------------------------------------
// Weight transpose: dst[c][k] = src[k][c], 1024x1024.
// ---------------------------------------------------------------------------
__global__ __launch_bounds__(256) void tr_w(const float* __restrict__ src,
                                            float* __restrict__ dst)
{
    __shared__ float t[32][33];
    int tx = threadIdx.x & 31, ty = threadIdx.x >> 5;
    int cb = blockIdx.x * 32, kb = blockIdx.y * 32;
    #pragma unroll
    for (int r = 0; r < 4; r++)
        t[ty + 8*r][tx] = src[(size_t)(kb + ty + 8*r)*DIMC + cb + tx];
    __syncthreads();
    #pragma unroll
    for (int r = 0; r < 4; r++)
        dst[(size_t)(cb + ty + 8*r)*DIMC + kb + tx] = t[tx][ty + 8*r];
}

// ---------------------------------------------------------------------------
// fp16 m16n8k16 mma.sync GEMM, double-buffered pipeline.
// 128x128 tile, K=1024 in 32 chunks of 32 (2 k16-steps each).
// 8 warps (4m x 2n), warp tile 32x64 = 2 mtiles x 8 ntiles.
// Smem rows: 32 halves = 16 u32 data, stride 20 u32 (conflict-free frags).
// mode 0: A = x, B = g_wt, scatter epilogue -> g_q/g_k/g_v
// mode 1: A = gathered g_o, B = g_wo_t, epilogue -> out (+bo)
// ---------------------------------------------------------------------------
#define MMW 20                 // u32 stride per row
#define MMSZ (128*MMW)

__global__ __launch_bounds__(256) void mm_mma(
    int mode,
    const float* __restrict__ x,
    const float* __restrict__ bq, const float* __restrict__ bk,
    const float* __restrict__ bv, const float* __restrict__ bo,
    float* __restrict__ out)
{
    __shared__ __align__(16) uint32_t As[2][MMSZ];
    __shared__ __align__(16) uint32_t Bs[2][MMSZ];

    const int tid = threadIdx.x, lane = tid & 31, w = tid >> 5;
    const int wm = w & 3, wn = w >> 2;
    const int rr = lane >> 2, qq = lane & 3;
    const int m0 = blockIdx.y * 128, c0 = blockIdx.x * 128;
    const float* Bsrc = (mode == 0) ? g_wt : g_wo_t;

    int rA[4], cA[4];
    #pragma unroll
    for (int i = 0; i < 4; i++) {
        int idx = tid + i*256;          // 0..1023 float4 slots (128 rows x 8)
        rA[i] = idx >> 3; cA[i] = idx & 7;
    }

    float acc[2][8][4];
    #pragma unroll
    for (int mt = 0; mt < 2; mt++)
        #pragma unroll
        for (int nt = 0; nt < 8; nt++)
            #pragma unroll
            for (int e = 0; e < 4; e++) acc[mt][nt][e] = 0.f;

    float4 pa[4], pb[4];

    auto fetch = [&](int kc) {
        const int k0 = kc * 32;
        #pragma unroll
        for (int i = 0; i < 4; i++) {
            int r = rA[i], c4 = cA[i];
            if (mode == 0) {
                pa[i] = *(const float4*)(x + (size_t)(m0 + r)*DIMC + k0 + c4*4);
            } else {
                int m = m0 + r, bz = m >> 11, n = m & (NN-1);
                int k = k0 + c4*4, h = k >> 6, d = k & 63;
                pa[i] = *(const float4*)(g_o + (((size_t)bz*HH + h)*NN + n)*HD + d);
            }
            pb[i] = *(const float4*)(Bsrc + (size_t)(c0 + r)*DIMC + k0 + c4*4);
        }
    };
    auto stage = [&](int b) {
        #pragma unroll
        for (int i = 0; i < 4; i++) {
            *(uint2*)&As[b][rA[i]*MMW + cA[i]*2] =
                make_uint2(f22u(pa[i].x, pa[i].y), f22u(pa[i].z, pa[i].w));
            *(uint2*)&Bs[b][rA[i]*MMW + cA[i]*2] =
                make_uint2(f22u(pb[i].x, pb[i].y), f22u(pb[i].z, pb[i].w));
        }
    };

    fetch(0);
    stage(0);
    __syncthreads();

    for (int kc = 0; kc < DIMC/32; kc++) {
        const int cur = kc & 1;
        if (kc + 1 < DIMC/32) fetch(kc + 1);

        const uint32_t* Ac = As[cur];
        const uint32_t* Bc = Bs[cur];
        #pragma unroll
        for (int ks = 0; ks < 2; ks++) {
            const int ku = ks * 8 + qq;
            uint32_t a[2][4];
            #pragma unroll
            for (int mt = 0; mt < 2; mt++) {
                int rm = wm*32 + mt*16 + rr;
                a[mt][0] = Ac[rm*MMW     + ku];
                a[mt][1] = Ac[(rm+8)*MMW + ku];
                a[mt][2] = Ac[rm*MMW     + ku + 4];
                a[mt][3] = Ac[(rm+8)*MMW + ku + 4];
            }
            #pragma unroll
            for (int nt = 0; nt < 8; nt++) {
                int cn = wn*64 + nt*8 + rr;
                uint32_t b0 = Bc[cn*MMW + ku];
                uint32_t b1 = Bc[cn*MMW + ku + 4];
                MMA_F16(acc[0][nt], a[0][0], a[0][1], a[0][2], a[0][3], b0, b1);
                MMA_F16(acc[1][nt], a[1][0], a[1][1], a[1][2], a[1][3], b0, b1);
            }
        }

        if (kc + 1 < DIMC/32) {
            stage(cur ^ 1);
            __syncthreads();
        }
    }

    // Epilogue
    #pragma unroll
    for (int mt = 0; mt < 2; mt++) {
        int r_lo = m0 + wm*32 + mt*16 + rr;
        int r_hi = r_lo + 8;
        #pragma unroll
        for (int nt = 0; nt < 8; nt++) {
            int c = c0 + wn*64 + nt*8 + qq*2;
            if (mode == 0) {
                #pragma unroll
                for (int e = 0; e < 4; e++) {
                    int cc = c + (e & 1);
                    int m  = (e < 2) ? r_lo : r_hi;
                    int bz = m >> 11, n = m & (NN-1);
                    float bias = (cc < DIMC) ? bq[cc]
                               : (cc < 2*DIMC) ? bk[cc - DIMC] : bv[cc - 2*DIMC];
                    float v = acc[mt][nt][e] + bias;
                    int h = cc / 192, t = cc % 192, d = t & 63;
                    float* dst = (t < 64) ? g_q : (t < 128) ? g_k : g_v;
                    dst[(((size_t)bz*HH + h)*NN + n)*HD + d] = v;
                }
            } else {
                float2 lo = make_float2(acc[mt][nt][0] + bo[c],
                                        acc[mt][nt][1] + bo[c+1]);
                float2 hi = make_float2(acc[mt][nt][2] + bo[c],
                                        acc[mt][nt][3] + bo[c+1]);
                *(float2*)(out + (size_t)r_lo*DIMC + c) = lo;
                *(float2*)(out + (size_t)r_hi*DIMC + c) = hi;
            }
        }
    }
}

// ---------------------------------------------------------------------------
// Fused per-head LayerNorm + RoPE for q AND k.  One warp per head row.
// ---------------------------------------------------------------------------
__global__ __launch_bounds__(256) void ln_rope(
    const float* __restrict__ qnw, const float* __restrict__ qnb,
    const float* __restrict__ knw, const float* __restrict__ knb,
    const float* __restrict__ cosb, const float* __restrict__ sinb)
{
    const int R = BB*HH*NN;
    int warp = (blockIdx.x * blockDim.x + threadIdx.x) >> 5;
    int lane = threadIdx.x & 31;
    int which = warp >= R;
    int wr = warp - (which ? R : 0);
    int bz = wr / (HH*NN);
    int n  = wr & (NN-1);

    const float* nw = which ? knw : qnw;
    const float* nb = which ? knb : qnb;
    float* row = (which ? g_k : g_q) + (size_t)wr * HD;

    float x1 = row[lane], x2 = row[lane + 32];
    float sum = x1 + x2;
    float sq  = x1*x1 + x2*x2;
    #pragma unroll
    for (int o = 16; o; o >>= 1) {
        sum += __shfl_xor_sync(0xffffffffu, sum, o);
        sq  += __shfl_xor_sync(0xffffffffu, sq,  o);
    }
    float mean = sum * (1.f/64.f);
    float var  = sq  * (1.f/64.f) - mean*mean;
    float inv  = rsqrtf(var + 1e-6f);
    float y1 = (x1 - mean) * inv * nw[lane]      + nb[lane];
    float y2 = (x2 - mean) * inv * nw[lane + 32] + nb[lane + 32];

    size_t rbase = ((size_t)bz*NN + n) * HD;
    float c1 = cosb[rbase + lane],      s1 = sinb[rbase + lane];
    float c2 = cosb[rbase + lane + 32], s2 = sinb[rbase + lane + 32];
    row[lane]      = y1*c1 - y2*s1;
    row[lane + 32] = y2*c2 + y1*s2;
}

// ---------------------------------------------------------------------------
// Flash attention via fp16 m16n8k16 mma.sync, v3.
// 128 threads / 4 warps; q-tile 128 rows (warp = 32 rows = 2 mtiles);
// k-tile 64 keys.  Q frags in registers.  P stays in registers
// (S C-frag layout == PV A-frag layout for fp16 k16 -> zero P smem traffic).
// Kh: [64 keys][64 d halves], stride 36 u32 -> S B-frags conflict-free.
// Vt: [64 d rows][keypair half2], stride 36 u32 -> PV B-frags conflict-free.
// ---------------------------------------------------------------------------
#define KST 36      // u32 stride for Kh / Vt rows

__global__ __launch_bounds__(128) void attn_mma()
{
    __shared__ __align__(16) uint32_t Kh[64*KST];
    __shared__ __align__(16) uint32_t Vt[64*KST];

    const int tid = threadIdx.x, lane = tid & 31, w = tid >> 5;   // w: 0..3
    const int bh = blockIdx.y;
    const int q0 = blockIdx.x * 128;
    const float* qb = g_q + (size_t)bh * NN * HD;
    const float* kb = g_k + (size_t)bh * NN * HD;
    const float* vb = g_v + (size_t)bh * NN * HD;

    const int rr = lane >> 2;       // 0..7
    const int qq = lane & 3;

    // Q A-fragments in registers (half2, scaled by HD^-0.5)
    uint32_t qf[2][4][4];           // [mtile][kstep16][reg]
    #pragma unroll
    for (int mt = 0; mt < 2; mt++) {
        int rbase = q0 + w*32 + mt*16 + rr;
        #pragma unroll
        for (int ks = 0; ks < 4; ks++) {
            int c = ks*16 + qq*2;
            float2 lo0 = *(const float2*)(qb + (size_t)rbase*HD     + c);
            float2 hi0 = *(const float2*)(qb + (size_t)(rbase+8)*HD + c);
            float2 lo8 = *(const float2*)(qb + (size_t)rbase*HD     + c + 8);
            float2 hi8 = *(const float2*)(qb + (size_t)(rbase+8)*HD + c + 8);
            qf[mt][ks][0] = f22u(lo0.x*0.125f, lo0.y*0.125f);
            qf[mt][ks][1] = f22u(hi0.x*0.125f, hi0.y*0.125f);
            qf[mt][ks][2] = f22u(lo8.x*0.125f, lo8.y*0.125f);
            qf[mt][ks][3] = f22u(hi8.x*0.125f, hi8.y*0.125f);
        }
    }

    float m_i[2][2], l_i[2][2];
    float o[2][8][4];
    #pragma unroll
    for (int mt = 0; mt < 2; mt++) {
        m_i[mt][0] = -1e30f; m_i[mt][1] = -1e30f;
        l_i[mt][0] = 0.f;    l_i[mt][1] = 0.f;
        #pragma unroll
        for (int nt = 0; nt < 8; nt++)
            #pragma unroll
            for (int e = 0; e < 4; e++) o[mt][nt][e] = 0.f;
    }

    for (int kt = 0; kt < NN/64; kt++) {
        const int k0 = kt * 64;
        __syncthreads();   // protect Kh/Vt reads of previous tile

        // Stage K: rows = keys, 64 halves (d), stride KST u32.  Conflict-free STS.64.
        #pragma unroll
        for (int i = 0; i < 8; i++) {
            int idx = tid + i*128;          // 0..1023 (64 rows x 16 float4)
            int r = idx >> 4, c4 = idx & 15;
            float4 kv = *(const float4*)(kb + (size_t)(k0 + r)*HD + c4*4);
            *(uint2*)&Kh[r*KST + c4*2] =
                make_uint2(f22u(kv.x, kv.y), f22u(kv.z, kv.w));
        }
        // Stage V transposed: Vt[d][keypair] half2 = (V[2m][d], V[2m+1][d]).
        #pragma unroll
        for (int i = 0; i < 4; i++) {
            int t = tid + i*128;            // 0..511 (32 keypairs x 16 dgroups)
            int m = t & 31, c = t >> 5;
            float4 v0 = *(const float4*)(vb + (size_t)(k0 + 2*m  )*HD + c*4);
            float4 v1 = *(const float4*)(vb + (size_t)(k0 + 2*m+1)*HD + c*4);
            Vt[(c*4+0)*KST + m] = f22u(v0.x, v1.x);
            Vt[(c*4+1)*KST + m] = f22u(v0.y, v1.y);
            Vt[(c*4+2)*KST + m] = f22u(v0.z, v1.z);
            Vt[(c*4+3)*KST + m] = f22u(v0.w, v1.w);
        }
        __syncthreads();

        uint32_t ph[2][8][2];   // P as half2 A-frag pieces [mt][nt][lo/hi]

        #pragma unroll
        for (int mt = 0; mt < 2; mt++) {
            float s[8][4];
            #pragma unroll
            for (int nt = 0; nt < 8; nt++)
                #pragma unroll
                for (int e = 0; e < 4; e++) s[nt][e] = 0.f;

            // S = Q @ K^T   (k-dim = 64 head dims, 4 k16 steps)
            #pragma unroll
            for (int ks = 0; ks < 4; ks++) {
                uint32_t a0 = qf[mt][ks][0], a1 = qf[mt][ks][1];
                uint32_t a2 = qf[mt][ks][2], a3 = qf[mt][ks][3];
                #pragma unroll
                for (int nt = 0; nt < 8; nt++) {
                    int cn = nt*8 + rr;
                    uint32_t b0 = Kh[cn*KST + ks*8 + qq];
                    uint32_t b1 = Kh[cn*KST + ks*8 + qq + 4];
                    MMA_F16(s[nt], a0, a1, a2, a3, b0, b1);
                }
            }

            // Online softmax (rows rr and rr+8 of this mtile)
            float tm_lo = -1e30f, tm_hi = -1e30f;
            #pragma unroll
            for (int nt = 0; nt < 8; nt++) {
                tm_lo = fmaxf(tm_lo, fmaxf(s[nt][0], s[nt][1]));
                tm_hi = fmaxf(tm_hi, fmaxf(s[nt][2], s[nt][3]));
            }
            #pragma unroll
            for (int off = 1; off <= 2; off <<= 1) {
                tm_lo = fmaxf(tm_lo, __shfl_xor_sync(0xffffffffu, tm_lo, off));
                tm_hi = fmaxf(tm_hi, __shfl_xor_sync(0xffffffffu, tm_hi, off));
            }
            float mn_lo = fmaxf(m_i[mt][0], tm_lo);
            float mn_hi = fmaxf(m_i[mt][1], tm_hi);
            float al_lo = __expf(m_i[mt][0] - mn_lo);
            float al_hi = __expf(m_i[mt][1] - mn_hi);
            m_i[mt][0] = mn_lo; m_i[mt][1] = mn_hi;
            float rs_lo = 0.f, rs_hi = 0.f;
            #pragma unroll
            for (int nt = 0; nt < 8; nt++) {
                s[nt][0] = __expf(s[nt][0] - mn_lo);
                s[nt][1] = __expf(s[nt][1] - mn_lo);
                s[nt][2] = __expf(s[nt][2] - mn_hi);
                s[nt][3] = __expf(s[nt][3] - mn_hi);
                rs_lo += s[nt][0] + s[nt][1];
                rs_hi += s[nt][2] + s[nt][3];
                ph[mt][nt][0] = f22u(s[nt][0], s[nt][1]);
                ph[mt][nt][1] = f22u(s[nt][2], s[nt][3]);
            }
            #pragma unroll
            for (int off = 1; off <= 2; off <<= 1) {
                rs_lo += __shfl_xor_sync(0xffffffffu, rs_lo, off);
                rs_hi += __shfl_xor_sync(0xffffffffu, rs_hi, off);
            }
            l_i[mt][0] = l_i[mt][0] * al_lo + rs_lo;
            l_i[mt][1] = l_i[mt][1] * al_hi + rs_hi;
            #pragma unroll
            for (int nt = 0; nt < 8; nt++) {
                o[mt][nt][0] *= al_lo; o[mt][nt][1] *= al_lo;
                o[mt][nt][2] *= al_hi; o[mt][nt][3] *= al_hi;
            }
        }

        // O += P @ V  (k-dim = 64 keys, 4 k16 steps; P direct from registers)
        #pragma unroll
        for (int g = 0; g < 4; g++) {
            #pragma unroll
            for (int nt = 0; nt < 8; nt++) {
                int cn = nt*8 + rr;             // output d index
                uint32_t b0 = Vt[cn*KST + g*8 + qq];
                uint32_t b1 = Vt[cn*KST + g*8 + qq + 4];
                MMA_F16(o[0][nt], ph[0][2*g][0], ph[0][2*g][1],
                                  ph[0][2*g+1][0], ph[0][2*g+1][1], b0, b1);
                MMA_F16(o[1][nt], ph[1][2*g][0], ph[1][2*g][1],
                                  ph[1][2*g+1][0], ph[1][2*g+1][1], b0, b1);
            }
        }
    }

    // Finalize
    #pragma unroll
    for (int mt = 0; mt < 2; mt++) {
        float inv_lo = 1.f / l_i[mt][0], inv_hi = 1.f / l_i[mt][1];
        int r_lo = q0 + w*32 + mt*16 + rr;
        int r_hi = r_lo + 8;
        #pragma unroll
        for (int nt = 0; nt < 8; nt++) {
            int c = nt*8 + qq*2;
            *(float2*)(g_o + ((size_t)bh*NN + r_lo)*HD + c) =
                make_float2(o[mt][nt][0]*inv_lo, o[mt][nt][1]*inv_lo);
            *(float2*)(g_o + ((size_t)bh*NN + r_hi)*HD + c) =
                make_float2(o[mt][nt][2]*inv_hi, o[mt][nt][3]*inv_hi);
        }
    }
}

// ---------------------------------------------------------------------------
extern "C" void kernel_launch(void* const* d_in, const int* in_sizes, int n_in,
                              void* d_out, int out_size)
{
    const float* x   = (const float*)d_in[0];
    const float* rc  = (const float*)d_in[1];
    const float* rs  = (const float*)d_in[2];
    const float* Wq  = (const float*)d_in[3];
    const float* bq  = (const float*)d_in[4];
    const float* Wk  = (const float*)d_in[5];
    const float* bk  = (const float*)d_in[6];
    const float* Wv  = (const float*)d_in[7];
    const float* bv  = (const float*)d_in[8];
    const float* qnw = (const float*)d_in[9];
    const float* qnb = (const float*)d_in[10];
    const float* knw = (const float*)d_in[11];
    const float* knb = (const float*)d_in[12];
    const float* Wo  = (const float*)d_in[13];
    const float* bo  = (const float*)d_in[14];
    float* out = (float*)d_out;

    float* d_wt;  cudaGetSymbolAddress((void**)&d_wt,  g_wt);
    float* d_wot; cudaGetSymbolAddress((void**)&d_wot, g_wo_t);

    tr_w<<<dim3(32, 32), 256>>>(Wq, d_wt);
    tr_w<<<dim3(32, 32), 256>>>(Wk, d_wt + DIMC*DIMC);
    tr_w<<<dim3(32, 32), 256>>>(Wv, d_wt + 2*DIMC*DIMC);
    tr_w<<<dim3(32, 32), 256>>>(Wo, d_wot);

    mm_mma<<<dim3(24, 32), 256>>>(0, x, bq, bk, bv, bo, out);

    const int warps2 = 2 * BB*HH*NN;           // q + k rows
    ln_rope<<<warps2/8, 256>>>(qnw, qnb, knw, knb, rc, rs);

    attn_mma<<<dim3(NN/128, BB*HH), 128>>>();

    mm_mma<<<dim3(8, 32), 256>>>(1, x, bq, bk, bv, bo, out);
}

// round 10
// speedup vs baseline: 4.2855x; 1.0533x over previous
#include <cuda_runtime.h>
#include <cuda_fp16.h>
#include <cstdint>

#define BB   2
#define NN   2048
#define DIMC 1024
#define HH   16
#define HD   64

// Scratch (allocation-free requirement)
__device__ float g_q[BB*HH*NN*HD];
__device__ float g_k[BB*HH*NN*HD];
__device__ float g_v[BB*HH*NN*HD];
__device__ float g_o[BB*HH*NN*HD];

// ---------------------------------------------------------------------------
__device__ __forceinline__ uint32_t f22u(float a, float b) {
    __half2 h = __floats2half2_rn(a, b);
    return *(uint32_t*)&h;
}
__device__ __forceinline__ float ex2(float x) {
    float y;
    asm("ex2.approx.f32 %0, %1;" : "=f"(y) : "f"(x));
    return y;
}

#define MMA_F16(c, a0, a1, a2, a3, b0, b1)                                    \
    asm volatile(                                                             \
        "mma.sync.aligned.m16n8k16.row.col.f32.f16.f16.f32 "                  \
        "{%0,%1,%2,%3}, {%4,%5,%6,%7}, {%8,%9}, {%0,%1,%2,%3};"               \
        : "+f"((c)[0]), "+f"((c)[1]), "+f"((c)[2]), "+f"((c)[3])              \
        : "r"(a0), "r"(a1), "r"(a2), "r"(a3), "r"(b0), "r"(b1))

// ---------------------------------------------------------------------------
// fp16 m16n8k16 mma.sync GEMM, double-buffered pipeline, direct-W staging.
// 128x128 tile, K=1024 in 32 chunks of 32 (2 k16-steps each).
// 8 warps (4m x 2n), warp tile 32x64 = 2 mtiles x 8 ntiles.
// A smem: [128 m rows][16 u32 kpairs], stride 20 (conflict-free A-frags).
// B smem: [16 kpair rows][128 c u32], stride 136 (136%32=8 -> B-frag lane
//   term 8*qq+rr covers 32 banks; staged from untransposed W by packing
//   rows (2k', 2k'+1) into half2 -> no weight pre-transpose needed).
// mode 0: A = x, B in {Wq,Wk,Wv} by c-tile, scatter epilogue -> g_q/g_k/g_v
// mode 1: A = gathered g_o, B = Wo, epilogue -> out (+bo)
// ---------------------------------------------------------------------------
#define MMW 20                 // A u32 stride per row
#define BW  136                // B u32 stride per kpair row

__global__ __launch_bounds__(256) void mm_mma(
    int mode,
    const float* __restrict__ x,
    const float* __restrict__ Wq, const float* __restrict__ Wk,
    const float* __restrict__ Wv, const float* __restrict__ Wo,
    const float* __restrict__ bq, const float* __restrict__ bk,
    const float* __restrict__ bv, const float* __restrict__ bo,
    float* __restrict__ out)
{
    __shared__ __align__(16) uint32_t As[2][128*MMW];
    __shared__ __align__(16) uint32_t Bs[2][16*BW];

    const int tid = threadIdx.x, lane = tid & 31, w = tid >> 5;
    const int wm = w & 3, wn = w >> 2;
    const int rr = lane >> 2, qq = lane & 3;
    const int m0 = blockIdx.y * 128, c0 = blockIdx.x * 128;

    const float* Wsel; int j0;
    if (mode == 1)            { Wsel = Wo; j0 = c0; }
    else if (c0 < DIMC)       { Wsel = Wq; j0 = c0; }
    else if (c0 < 2*DIMC)     { Wsel = Wk; j0 = c0 - DIMC; }
    else                      { Wsel = Wv; j0 = c0 - 2*DIMC; }

    // A slots: 1024 float4 (128 rows x 8); B slots: 512 (16 kpairs x 32 c4)
    int rA[4], cA[4];
    #pragma unroll
    for (int i = 0; i < 4; i++) {
        int idx = tid + i*256;
        rA[i] = idx >> 3; cA[i] = idx & 7;
    }
    int kB[2], cB[2];
    #pragma unroll
    for (int i = 0; i < 2; i++) {
        int idx = tid + i*256;
        kB[i] = idx >> 5; cB[i] = idx & 31;
    }

    float acc[2][8][4];
    #pragma unroll
    for (int mt = 0; mt < 2; mt++)
        #pragma unroll
        for (int nt = 0; nt < 8; nt++)
            #pragma unroll
            for (int e = 0; e < 4; e++) acc[mt][nt][e] = 0.f;

    float4 pa[4], pb0[2], pb1[2];

    auto fetch = [&](int kc) {
        const int k0 = kc * 32;
        #pragma unroll
        for (int i = 0; i < 4; i++) {
            int r = rA[i], c4 = cA[i];
            if (mode == 0) {
                pa[i] = *(const float4*)(x + (size_t)(m0 + r)*DIMC + k0 + c4*4);
            } else {
                int m = m0 + r, bz = m >> 11, n = m & (NN-1);
                int k = k0 + c4*4, h = k >> 6, d = k & 63;
                pa[i] = *(const float4*)(g_o + (((size_t)bz*HH + h)*NN + n)*HD + d);
            }
        }
        #pragma unroll
        for (int i = 0; i < 2; i++) {
            const float* p = Wsel + (size_t)(k0 + 2*kB[i])*DIMC + j0 + cB[i]*4;
            pb0[i] = *(const float4*)(p);
            pb1[i] = *(const float4*)(p + DIMC);
        }
    };
    auto stage = [&](int b) {
        #pragma unroll
        for (int i = 0; i < 4; i++)
            *(uint2*)&As[b][rA[i]*MMW + cA[i]*2] =
                make_uint2(f22u(pa[i].x, pa[i].y), f22u(pa[i].z, pa[i].w));
        #pragma unroll
        for (int i = 0; i < 2; i++) {
            uint4 v;
            v.x = f22u(pb0[i].x, pb1[i].x);
            v.y = f22u(pb0[i].y, pb1[i].y);
            v.z = f22u(pb0[i].z, pb1[i].z);
            v.w = f22u(pb0[i].w, pb1[i].w);
            *(uint4*)&Bs[b][kB[i]*BW + cB[i]*4] = v;
        }
    };

    fetch(0);
    stage(0);
    __syncthreads();

    for (int kc = 0; kc < DIMC/32; kc++) {
        const int cur = kc & 1;
        if (kc + 1 < DIMC/32) fetch(kc + 1);

        const uint32_t* Ac = As[cur];
        const uint32_t* Bc = Bs[cur];
        #pragma unroll
        for (int ks = 0; ks < 2; ks++) {
            const int ku = ks * 8 + qq;
            uint32_t a[2][4];
            #pragma unroll
            for (int mt = 0; mt < 2; mt++) {
                int rm = wm*32 + mt*16 + rr;
                a[mt][0] = Ac[rm*MMW     + ku];
                a[mt][1] = Ac[(rm+8)*MMW + ku];
                a[mt][2] = Ac[rm*MMW     + ku + 4];
                a[mt][3] = Ac[(rm+8)*MMW + ku + 4];
            }
            #pragma unroll
            for (int nt = 0; nt < 8; nt++) {
                int cn = wn*64 + nt*8 + rr;
                uint32_t b0 = Bc[(ks*8 + qq)*BW     + cn];
                uint32_t b1 = Bc[(ks*8 + qq + 4)*BW + cn];
                MMA_F16(acc[0][nt], a[0][0], a[0][1], a[0][2], a[0][3], b0, b1);
                MMA_F16(acc[1][nt], a[1][0], a[1][1], a[1][2], a[1][3], b0, b1);
            }
        }

        if (kc + 1 < DIMC/32) {
            stage(cur ^ 1);
            __syncthreads();
        }
    }

    // Epilogue
    #pragma unroll
    for (int mt = 0; mt < 2; mt++) {
        int r_lo = m0 + wm*32 + mt*16 + rr;
        int r_hi = r_lo + 8;
        #pragma unroll
        for (int nt = 0; nt < 8; nt++) {
            int c = c0 + wn*64 + nt*8 + qq*2;
            if (mode == 0) {
                #pragma unroll
                for (int e = 0; e < 4; e++) {
                    int cc = c + (e & 1);
                    int m  = (e < 2) ? r_lo : r_hi;
                    int bz = m >> 11, n = m & (NN-1);
                    float bias = (cc < DIMC) ? bq[cc]
                               : (cc < 2*DIMC) ? bk[cc - DIMC] : bv[cc - 2*DIMC];
                    float v = acc[mt][nt][e] + bias;
                    int h = cc / 192, t = cc % 192, d = t & 63;
                    float* dst = (t < 64) ? g_q : (t < 128) ? g_k : g_v;
                    dst[(((size_t)bz*HH + h)*NN + n)*HD + d] = v;
                }
            } else {
                float2 lo = make_float2(acc[mt][nt][0] + bo[c],
                                        acc[mt][nt][1] + bo[c+1]);
                float2 hi = make_float2(acc[mt][nt][2] + bo[c],
                                        acc[mt][nt][3] + bo[c+1]);
                *(float2*)(out + (size_t)r_lo*DIMC + c) = lo;
                *(float2*)(out + (size_t)r_hi*DIMC + c) = hi;
            }
        }
    }
}

// ---------------------------------------------------------------------------
// Fused per-head LayerNorm + RoPE for q AND k.  One warp per head row.
// ---------------------------------------------------------------------------
__global__ __launch_bounds__(256) void ln_rope(
    const float* __restrict__ qnw, const float* __restrict__ qnb,
    const float* __restrict__ knw, const float* __restrict__ knb,
    const float* __restrict__ cosb, const float* __restrict__ sinb)
{
    const int R = BB*HH*NN;
    int warp = (blockIdx.x * blockDim.x + threadIdx.x) >> 5;
    int lane = threadIdx.x & 31;
    int which = warp >= R;
    int wr = warp - (which ? R : 0);
    int bz = wr / (HH*NN);
    int n  = wr & (NN-1);

    const float* nw = which ? knw : qnw;
    const float* nb = which ? knb : qnb;
    float* row = (which ? g_k : g_q) + (size_t)wr * HD;

    float x1 = row[lane], x2 = row[lane + 32];
    float sum = x1 + x2;
    float sq  = x1*x1 + x2*x2;
    #pragma unroll
    for (int o = 16; o; o >>= 1) {
        sum += __shfl_xor_sync(0xffffffffu, sum, o);
        sq  += __shfl_xor_sync(0xffffffffu, sq,  o);
    }
    float mean = sum * (1.f/64.f);
    float var  = sq  * (1.f/64.f) - mean*mean;
    float inv  = rsqrtf(var + 1e-6f);
    float y1 = (x1 - mean) * inv * nw[lane]      + nb[lane];
    float y2 = (x2 - mean) * inv * nw[lane + 32] + nb[lane + 32];

    size_t rbase = ((size_t)bz*NN + n) * HD;
    float c1 = cosb[rbase + lane],      s1 = sinb[rbase + lane];
    float c2 = cosb[rbase + lane + 32], s2 = sinb[rbase + lane + 32];
    row[lane]      = y1*c1 - y2*s1;
    row[lane + 32] = y2*c2 + y1*s2;
}

// ---------------------------------------------------------------------------
// Flash attention via fp16 m16n8k16 mma.sync, v4 (no-max softmax).
// Scores are LN-normalized (~N(0,1)) -> exp never overflows fp32; drop the
// running max, alpha rescales, and max shuffles.  Q pre-scaled by
// HD^-0.5 * log2(e); probabilities via raw ex2.approx.
// 128 threads / 4 warps; q-tile 128 rows; k-tile 64 keys; P in registers.
// ---------------------------------------------------------------------------
#define KST 36      // u32 stride for Kh / Vt rows

__global__ __launch_bounds__(128) void attn_mma()
{
    __shared__ __align__(16) uint32_t Kh[64*KST];
    __shared__ __align__(16) uint32_t Vt[64*KST];

    const int tid = threadIdx.x, lane = tid & 31, w = tid >> 5;   // w: 0..3
    const int bh = blockIdx.y;
    const int q0 = blockIdx.x * 128;
    const float* qb = g_q + (size_t)bh * NN * HD;
    const float* kb = g_k + (size_t)bh * NN * HD;
    const float* vb = g_v + (size_t)bh * NN * HD;

    const int rr = lane >> 2;       // 0..7
    const int qq = lane & 3;
    const float QS = 0.125f * 1.4426950408889634f;   // HD^-0.5 * log2(e)

    // Q A-fragments in registers (half2, pre-scaled)
    uint32_t qf[2][4][4];           // [mtile][kstep16][reg]
    #pragma unroll
    for (int mt = 0; mt < 2; mt++) {
        int rbase = q0 + w*32 + mt*16 + rr;
        #pragma unroll
        for (int ks = 0; ks < 4; ks++) {
            int c = ks*16 + qq*2;
            float2 lo0 = *(const float2*)(qb + (size_t)rbase*HD     + c);
            float2 hi0 = *(const float2*)(qb + (size_t)(rbase+8)*HD + c);
            float2 lo8 = *(const float2*)(qb + (size_t)rbase*HD     + c + 8);
            float2 hi8 = *(const float2*)(qb + (size_t)(rbase+8)*HD + c + 8);
            qf[mt][ks][0] = f22u(lo0.x*QS, lo0.y*QS);
            qf[mt][ks][1] = f22u(hi0.x*QS, hi0.y*QS);
            qf[mt][ks][2] = f22u(lo8.x*QS, lo8.y*QS);
            qf[mt][ks][3] = f22u(hi8.x*QS, hi8.y*QS);
        }
    }

    float l_i[2][2];
    float o[2][8][4];
    #pragma unroll
    for (int mt = 0; mt < 2; mt++) {
        l_i[mt][0] = 0.f; l_i[mt][1] = 0.f;
        #pragma unroll
        for (int nt = 0; nt < 8; nt++)
            #pragma unroll
            for (int e = 0; e < 4; e++) o[mt][nt][e] = 0.f;
    }

    for (int kt = 0; kt < NN/64; kt++) {
        const int k0 = kt * 64;
        __syncthreads();   // protect Kh/Vt reads of previous tile

        // Stage K: rows = keys, 64 halves (d), stride KST u32.
        #pragma unroll
        for (int i = 0; i < 8; i++) {
            int idx = tid + i*128;          // 0..1023 (64 rows x 16 float4)
            int r = idx >> 4, c4 = idx & 15;
            float4 kv = *(const float4*)(kb + (size_t)(k0 + r)*HD + c4*4);
            *(uint2*)&Kh[r*KST + c4*2] =
                make_uint2(f22u(kv.x, kv.y), f22u(kv.z, kv.w));
        }
        // Stage V transposed: Vt[d][keypair] half2 = (V[2m][d], V[2m+1][d]).
        #pragma unroll
        for (int i = 0; i < 4; i++) {
            int t = tid + i*128;            // 0..511 (32 keypairs x 16 dgroups)
            int m = t & 31, c = t >> 5;
            float4 v0 = *(const float4*)(vb + (size_t)(k0 + 2*m  )*HD + c*4);
            float4 v1 = *(const float4*)(vb + (size_t)(k0 + 2*m+1)*HD + c*4);
            Vt[(c*4+0)*KST + m] = f22u(v0.x, v1.x);
            Vt[(c*4+1)*KST + m] = f22u(v0.y, v1.y);
            Vt[(c*4+2)*KST + m] = f22u(v0.z, v1.z);
            Vt[(c*4+3)*KST + m] = f22u(v0.w, v1.w);
        }
        __syncthreads();

        uint32_t ph[2][8][2];   // P as half2 A-frag pieces [mt][nt][lo/hi]

        #pragma unroll
        for (int mt = 0; mt < 2; mt++) {
            float s[8][4];
            #pragma unroll
            for (int nt = 0; nt < 8; nt++)
                #pragma unroll
                for (int e = 0; e < 4; e++) s[nt][e] = 0.f;

            // S = Q @ K^T   (k-dim = 64 head dims, 4 k16 steps)
            #pragma unroll
            for (int ks = 0; ks < 4; ks++) {
                uint32_t a0 = qf[mt][ks][0], a1 = qf[mt][ks][1];
                uint32_t a2 = qf[mt][ks][2], a3 = qf[mt][ks][3];
                #pragma unroll
                for (int nt = 0; nt < 8; nt++) {
                    int cn = nt*8 + rr;
                    uint32_t b0 = Kh[cn*KST + ks*8 + qq];
                    uint32_t b1 = Kh[cn*KST + ks*8 + qq + 4];
                    MMA_F16(s[nt], a0, a1, a2, a3, b0, b1);
                }
            }

            // Softmax numerators (no max shift; scores are O(1) normalized)
            float rs_lo = 0.f, rs_hi = 0.f;
            #pragma unroll
            for (int nt = 0; nt < 8; nt++) {
                s[nt][0] = ex2(s[nt][0]);
                s[nt][1] = ex2(s[nt][1]);
                s[nt][2] = ex2(s[nt][2]);
                s[nt][3] = ex2(s[nt][3]);
                rs_lo += s[nt][0] + s[nt][1];
                rs_hi += s[nt][2] + s[nt][3];
                ph[mt][nt][0] = f22u(s[nt][0], s[nt][1]);
                ph[mt][nt][1] = f22u(s[nt][2], s[nt][3]);
            }
            #pragma unroll
            for (int off = 1; off <= 2; off <<= 1) {
                rs_lo += __shfl_xor_sync(0xffffffffu, rs_lo, off);
                rs_hi += __shfl_xor_sync(0xffffffffu, rs_hi, off);
            }
            l_i[mt][0] += rs_lo;
            l_i[mt][1] += rs_hi;
        }

        // O += P @ V  (k-dim = 64 keys, 4 k16 steps; P direct from registers)
        #pragma unroll
        for (int g = 0; g < 4; g++) {
            #pragma unroll
            for (int nt = 0; nt < 8; nt++) {
                int cn = nt*8 + rr;             // output d index
                uint32_t b0 = Vt[cn*KST + g*8 + qq];
                uint32_t b1 = Vt[cn*KST + g*8 + qq + 4];
                MMA_F16(o[0][nt], ph[0][2*g][0], ph[0][2*g][1],
                                  ph[0][2*g+1][0], ph[0][2*g+1][1], b0, b1);
                MMA_F16(o[1][nt], ph[1][2*g][0], ph[1][2*g][1],
                                  ph[1][2*g+1][0], ph[1][2*g+1][1], b0, b1);
            }
        }
    }

    // Finalize
    #pragma unroll
    for (int mt = 0; mt < 2; mt++) {
        float inv_lo = 1.f / l_i[mt][0], inv_hi = 1.f / l_i[mt][1];
        int r_lo = q0 + w*32 + mt*16 + rr;
        int r_hi = r_lo + 8;
        #pragma unroll
        for (int nt = 0; nt < 8; nt++) {
            int c = nt*8 + qq*2;
            *(float2*)(g_o + ((size_t)bh*NN + r_lo)*HD + c) =
                make_float2(o[mt][nt][0]*inv_lo, o[mt][nt][1]*inv_lo);
            *(float2*)(g_o + ((size_t)bh*NN + r_hi)*HD + c) =
                make_float2(o[mt][nt][2]*inv_hi, o[mt][nt][3]*inv_hi);
        }
    }
}

// ---------------------------------------------------------------------------
extern "C" void kernel_launch(void* const* d_in, const int* in_sizes, int n_in,
                              void* d_out, int out_size)
{
    const float* x   = (const float*)d_in[0];
    const float* rc  = (const float*)d_in[1];
    const float* rs  = (const float*)d_in[2];
    const float* Wq  = (const float*)d_in[3];
    const float* bq  = (const float*)d_in[4];
    const float* Wk  = (const float*)d_in[5];
    const float* bk  = (const float*)d_in[6];
    const float* Wv  = (const float*)d_in[7];
    const float* bv  = (const float*)d_in[8];
    const float* qnw = (const float*)d_in[9];
    const float* qnb = (const float*)d_in[10];
    const float* knw = (const float*)d_in[11];
    const float* knb = (const float*)d_in[12];
    const float* Wo  = (const float*)d_in[13];
    const float* bo  = (const float*)d_in[14];
    float* out = (float*)d_out;

    mm_mma<<<dim3(24, 32), 256>>>(0, x, Wq, Wk, Wv, Wo,
                                  bq, bk, bv, bo, out);

    const int warps2 = 2 * BB*HH*NN;           // q + k rows
    ln_rope<<<warps2/8, 256>>>(qnw, qnb, knw, knb, rc, rs);

    attn_mma<<<dim3(NN/128, BB*HH), 128>>>();

    mm_mma<<<dim3(8, 32), 256>>>(1, x, Wq, Wk, Wv, Wo,
                                 bq, bk, bv, bo, out);
}

// round 11
// speedup vs baseline: 5.2937x; 1.2353x over previous
#include <cuda_runtime.h>
#include <cuda_fp16.h>
#include <cstdint>

#define BB   2
#define NN   2048
#define DIMC 1024
#define HH   16
#define HD   64

// Scratch (allocation-free requirement)
__device__ float    g_q[BB*HH*NN*HD];
__device__ float    g_k[BB*HH*NN*HD];
__device__ float    g_v[BB*HH*NN*HD];
__device__ uint32_t g_xh[BB*NN*DIMC/2];     // x as half2 pairs  [4096][512]
__device__ uint32_t g_oh[BB*NN*DIMC/2];     // attn out as half2 [4096][512]
__device__ uint32_t g_wh[4*(DIMC/2)*DIMC];  // W{q,k,v,o} kpair-packed half2

// ---------------------------------------------------------------------------
__device__ __forceinline__ uint32_t f22u(float a, float b) {
    __half2 h = __floats2half2_rn(a, b);
    return *(uint32_t*)&h;
}
__device__ __forceinline__ float ex2(float x) {
    float y;
    asm("ex2.approx.f32 %0, %1;" : "=f"(y) : "f"(x));
    return y;
}
__device__ __forceinline__ void cp16(void* dst, const void* src) {
    uint32_t sa = (uint32_t)__cvta_generic_to_shared(dst);
    asm volatile("cp.async.cg.shared.global [%0], [%1], 16;"
                 :: "r"(sa), "l"(src));
}
#define CP_COMMIT() asm volatile("cp.async.commit_group;")
#define CP_WAIT(n)  asm volatile("cp.async.wait_group %0;" :: "n"(n))

#define MMA_F16(c, a0, a1, a2, a3, b0, b1)                                    \
    asm volatile(                                                             \
        "mma.sync.aligned.m16n8k16.row.col.f32.f16.f16.f32 "                  \
        "{%0,%1,%2,%3}, {%4,%5,%6,%7}, {%8,%9}, {%0,%1,%2,%3};"               \
        : "+f"((c)[0]), "+f"((c)[1]), "+f"((c)[2]), "+f"((c)[3])              \
        : "r"(a0), "r"(a1), "r"(a2), "r"(a3), "r"(b0), "r"(b1))

// ---------------------------------------------------------------------------
// x -> fp16 half2 pairs.  1M float4 reads -> 1M uint2 writes.
// ---------------------------------------------------------------------------
__global__ __launch_bounds__(256) void cvt_x(const float* __restrict__ x)
{
    int i = blockIdx.x * blockDim.x + threadIdx.x;     // 0..1048575
    float4 v = ((const float4*)x)[i];
    ((uint2*)g_xh)[i] = make_uint2(f22u(v.x, v.y), f22u(v.z, v.w));
}

// ---------------------------------------------------------------------------
// Weights -> kpair-packed fp16: g_wh[mat][kp][c] = half2(W[2kp][c], W[2kp+1][c]).
// 4 matrices x 512 kpairs x 256 col-quads.
// ---------------------------------------------------------------------------
__global__ __launch_bounds__(256) void cvt_w(
    const float* __restrict__ Wq, const float* __restrict__ Wk,
    const float* __restrict__ Wv, const float* __restrict__ Wo)
{
    int idx = blockIdx.x * blockDim.x + threadIdx.x;   // 0..524287
    int mat = idx >> 17;
    int kp  = (idx >> 8) & 511;
    int c4  = idx & 255;
    const float* W = (mat == 0) ? Wq : (mat == 1) ? Wk : (mat == 2) ? Wv : Wo;
    const float4 r0 = *(const float4*)(W + (size_t)(2*kp  )*DIMC + c4*4);
    const float4 r1 = *(const float4*)(W + (size_t)(2*kp+1)*DIMC + c4*4);
    uint4 o;
    o.x = f22u(r0.x, r1.x); o.y = f22u(r0.y, r1.y);
    o.z = f22u(r0.z, r1.z); o.w = f22u(r0.w, r1.w);
    *(uint4*)&g_wh[((size_t)mat*512 + kp)*DIMC + c4*4] = o;
}

// ---------------------------------------------------------------------------
// fp16 m16n8k16 GEMM, 3-stage cp.async pipeline, all-fp16 sources.
// 128x128 tile, K=1024 in 32 chunks of 32.  8 warps (4m x 2n).
// A smem: [128 rows][16 u32 kpairs] stride 20; B smem: [16 kpairs][128 c]
// stride 136.  mode 0: A=g_xh, B by c-tile in {Wq,Wk,Wv}, scatter -> q/k/v.
// mode 1: A=g_oh (gather pre-baked by attention), B=Wo, out (+bo).
// ---------------------------------------------------------------------------
#define MMW 20
#define BWW 136
#define ASZ (128*MMW)   // 2560 u32
#define BSZ (16*BWW)    // 2176 u32
#define MM_SMEM (3*(ASZ+BSZ)*4)   // 56832 B

__global__ __launch_bounds__(256, 2) void mm_mma(
    int mode,
    const float* __restrict__ bq, const float* __restrict__ bk,
    const float* __restrict__ bv, const float* __restrict__ bo,
    float* __restrict__ out)
{
    extern __shared__ __align__(16) uint32_t dsm[];
    uint32_t* As = dsm;                 // [3][ASZ]
    uint32_t* Bs = dsm + 3*ASZ;         // [3][BSZ]

    const int tid = threadIdx.x, lane = tid & 31, w = tid >> 5;
    const int wm = w & 3, wn = w >> 2;
    const int rr = lane >> 2, qq = lane & 3;
    const int m0 = blockIdx.y * 128, c0 = blockIdx.x * 128;

    const uint32_t* Asrc = mode ? g_oh : g_xh;
    int mat, j0;
    if (mode == 1) { mat = 3; j0 = c0; }
    else           { mat = c0 >> 10; j0 = c0 & 1023; }
    const uint32_t* Bsrc = g_wh + (size_t)mat * 512 * DIMC;

    // A: 512 16B-chunks (128 rows x 4); B: 512 (16 kpairs x 32)
    const int ra0 = tid >> 2,       ca0 = tid & 3;
    const int ra1 = (tid+256) >> 2, ca1 = (tid+256) & 3;
    const int kb0 = tid >> 5,       cb0 = tid & 31;
    const int kb1 = (tid+256) >> 5, cb1 = (tid+256) & 31;

    auto issue = [&](int kc, int s) {
        const int kp0 = kc * 16;
        cp16(&As[s*ASZ + ra0*MMW + ca0*4],
             Asrc + (size_t)(m0 + ra0)*512 + kp0 + ca0*4);
        cp16(&As[s*ASZ + ra1*MMW + ca1*4],
             Asrc + (size_t)(m0 + ra1)*512 + kp0 + ca1*4);
        cp16(&Bs[s*BSZ + kb0*BWW + cb0*4],
             Bsrc + (size_t)(kp0 + kb0)*DIMC + j0 + cb0*4);
        cp16(&Bs[s*BSZ + kb1*BWW + cb1*4],
             Bsrc + (size_t)(kp0 + kb1)*DIMC + j0 + cb1*4);
        CP_COMMIT();
    };

    float acc[2][8][4];
    #pragma unroll
    for (int mt = 0; mt < 2; mt++)
        #pragma unroll
        for (int nt = 0; nt < 8; nt++)
            #pragma unroll
            for (int e = 0; e < 4; e++) acc[mt][nt][e] = 0.f;

    issue(0, 0);
    issue(1, 1);

    for (int kc = 0; kc < DIMC/32; kc++) {
        if (kc < DIMC/32 - 2) { CP_WAIT(1); } else { CP_WAIT(0); }
        __syncthreads();

        const uint32_t* Ac = &As[(kc % 3)*ASZ];
        const uint32_t* Bc = &Bs[(kc % 3)*BSZ];
        #pragma unroll
        for (int ks = 0; ks < 2; ks++) {
            const int ku = ks * 8 + qq;
            uint32_t a[2][4];
            #pragma unroll
            for (int mt = 0; mt < 2; mt++) {
                int rm = wm*32 + mt*16 + rr;
                a[mt][0] = Ac[rm*MMW     + ku];
                a[mt][1] = Ac[(rm+8)*MMW + ku];
                a[mt][2] = Ac[rm*MMW     + ku + 4];
                a[mt][3] = Ac[(rm+8)*MMW + ku + 4];
            }
            #pragma unroll
            for (int nt = 0; nt < 8; nt++) {
                int cn = wn*64 + nt*8 + rr;
                uint32_t b0 = Bc[(ks*8 + qq)*BWW     + cn];
                uint32_t b1 = Bc[(ks*8 + qq + 4)*BWW + cn];
                MMA_F16(acc[0][nt], a[0][0], a[0][1], a[0][2], a[0][3], b0, b1);
                MMA_F16(acc[1][nt], a[1][0], a[1][1], a[1][2], a[1][3], b0, b1);
            }
        }

        if (kc + 2 < DIMC/32) issue(kc + 2, (kc + 2) % 3);
    }

    // Epilogue
    #pragma unroll
    for (int mt = 0; mt < 2; mt++) {
        int r_lo = m0 + wm*32 + mt*16 + rr;
        int r_hi = r_lo + 8;
        #pragma unroll
        for (int nt = 0; nt < 8; nt++) {
            int c = c0 + wn*64 + nt*8 + qq*2;
            if (mode == 0) {
                #pragma unroll
                for (int e = 0; e < 4; e++) {
                    int cc = c + (e & 1);
                    int m  = (e < 2) ? r_lo : r_hi;
                    int bz = m >> 11, n = m & (NN-1);
                    float bias = (cc < DIMC) ? bq[cc]
                               : (cc < 2*DIMC) ? bk[cc - DIMC] : bv[cc - 2*DIMC];
                    float v = acc[mt][nt][e] + bias;
                    int h = cc / 192, t = cc % 192, d = t & 63;
                    float* dst = (t < 64) ? g_q : (t < 128) ? g_k : g_v;
                    dst[(((size_t)bz*HH + h)*NN + n)*HD + d] = v;
                }
            } else {
                float2 lo = make_float2(acc[mt][nt][0] + bo[c],
                                        acc[mt][nt][1] + bo[c+1]);
                float2 hi = make_float2(acc[mt][nt][2] + bo[c],
                                        acc[mt][nt][3] + bo[c+1]);
                *(float2*)(out + (size_t)r_lo*DIMC + c) = lo;
                *(float2*)(out + (size_t)r_hi*DIMC + c) = hi;
            }
        }
    }
}

// ---------------------------------------------------------------------------
// Fused per-head LayerNorm + RoPE for q AND k.  One warp per head row.
// ---------------------------------------------------------------------------
__global__ __launch_bounds__(256) void ln_rope(
    const float* __restrict__ qnw, const float* __restrict__ qnb,
    const float* __restrict__ knw, const float* __restrict__ knb,
    const float* __restrict__ cosb, const float* __restrict__ sinb)
{
    const int R = BB*HH*NN;
    int warp = (blockIdx.x * blockDim.x + threadIdx.x) >> 5;
    int lane = threadIdx.x & 31;
    int which = warp >= R;
    int wr = warp - (which ? R : 0);
    int bz = wr / (HH*NN);
    int n  = wr & (NN-1);

    const float* nw = which ? knw : qnw;
    const float* nb = which ? knb : qnb;
    float* row = (which ? g_k : g_q) + (size_t)wr * HD;

    float x1 = row[lane], x2 = row[lane + 32];
    float sum = x1 + x2;
    float sq  = x1*x1 + x2*x2;
    #pragma unroll
    for (int o = 16; o; o >>= 1) {
        sum += __shfl_xor_sync(0xffffffffu, sum, o);
        sq  += __shfl_xor_sync(0xffffffffu, sq,  o);
    }
    float mean = sum * (1.f/64.f);
    float var  = sq  * (1.f/64.f) - mean*mean;
    float inv  = rsqrtf(var + 1e-6f);
    float y1 = (x1 - mean) * inv * nw[lane]      + nb[lane];
    float y2 = (x2 - mean) * inv * nw[lane + 32] + nb[lane + 32];

    size_t rbase = ((size_t)bz*NN + n) * HD;
    float c1 = cosb[rbase + lane],      s1 = sinb[rbase + lane];
    float c2 = cosb[rbase + lane + 32], s2 = sinb[rbase + lane + 32];
    row[lane]      = y1*c1 - y2*s1;
    row[lane + 32] = y2*c2 + y1*s2;
}

// ---------------------------------------------------------------------------
// Flash attention via fp16 m16n8k16 mma.sync, v4 (no-max softmax).
// Output written directly as fp16 half2 into the gathered [m][h*64+d]
// layout consumed by the out-projection (g_oh) -- identical rounding to
// what the GEMM staging performed before, zero extra error.
// ---------------------------------------------------------------------------
#define KST 36      // u32 stride for Kh / Vt rows

__global__ __launch_bounds__(128) void attn_mma()
{
    __shared__ __align__(16) uint32_t Kh[64*KST];
    __shared__ __align__(16) uint32_t Vt[64*KST];

    const int tid = threadIdx.x, lane = tid & 31, w = tid >> 5;   // w: 0..3
    const int bh = blockIdx.y;
    const int q0 = blockIdx.x * 128;
    const float* qb = g_q + (size_t)bh * NN * HD;
    const float* kb = g_k + (size_t)bh * NN * HD;
    const float* vb = g_v + (size_t)bh * NN * HD;

    const int rr = lane >> 2;       // 0..7
    const int qq = lane & 3;
    const float QS = 0.125f * 1.4426950408889634f;   // HD^-0.5 * log2(e)

    // Q A-fragments in registers (half2, pre-scaled)
    uint32_t qf[2][4][4];           // [mtile][kstep16][reg]
    #pragma unroll
    for (int mt = 0; mt < 2; mt++) {
        int rbase = q0 + w*32 + mt*16 + rr;
        #pragma unroll
        for (int ks = 0; ks < 4; ks++) {
            int c = ks*16 + qq*2;
            float2 lo0 = *(const float2*)(qb + (size_t)rbase*HD     + c);
            float2 hi0 = *(const float2*)(qb + (size_t)(rbase+8)*HD + c);
            float2 lo8 = *(const float2*)(qb + (size_t)rbase*HD     + c + 8);
            float2 hi8 = *(const float2*)(qb + (size_t)(rbase+8)*HD + c + 8);
            qf[mt][ks][0] = f22u(lo0.x*QS, lo0.y*QS);
            qf[mt][ks][1] = f22u(hi0.x*QS, hi0.y*QS);
            qf[mt][ks][2] = f22u(lo8.x*QS, lo8.y*QS);
            qf[mt][ks][3] = f22u(hi8.x*QS, hi8.y*QS);
        }
    }

    float l_i[2][2];
    float o[2][8][4];
    #pragma unroll
    for (int mt = 0; mt < 2; mt++) {
        l_i[mt][0] = 0.f; l_i[mt][1] = 0.f;
        #pragma unroll
        for (int nt = 0; nt < 8; nt++)
            #pragma unroll
            for (int e = 0; e < 4; e++) o[mt][nt][e] = 0.f;
    }

    for (int kt = 0; kt < NN/64; kt++) {
        const int k0 = kt * 64;
        __syncthreads();   // protect Kh/Vt reads of previous tile

        #pragma unroll
        for (int i = 0; i < 8; i++) {
            int idx = tid + i*128;          // 0..1023 (64 rows x 16 float4)
            int r = idx >> 4, c4 = idx & 15;
            float4 kv = *(const float4*)(kb + (size_t)(k0 + r)*HD + c4*4);
            *(uint2*)&Kh[r*KST + c4*2] =
                make_uint2(f22u(kv.x, kv.y), f22u(kv.z, kv.w));
        }
        #pragma unroll
        for (int i = 0; i < 4; i++) {
            int t = tid + i*128;            // 0..511 (32 keypairs x 16 dgroups)
            int m = t & 31, c = t >> 5;
            float4 v0 = *(const float4*)(vb + (size_t)(k0 + 2*m  )*HD + c*4);
            float4 v1 = *(const float4*)(vb + (size_t)(k0 + 2*m+1)*HD + c*4);
            Vt[(c*4+0)*KST + m] = f22u(v0.x, v1.x);
            Vt[(c*4+1)*KST + m] = f22u(v0.y, v1.y);
            Vt[(c*4+2)*KST + m] = f22u(v0.z, v1.z);
            Vt[(c*4+3)*KST + m] = f22u(v0.w, v1.w);
        }
        __syncthreads();

        uint32_t ph[2][8][2];

        #pragma unroll
        for (int mt = 0; mt < 2; mt++) {
            float s[8][4];
            #pragma unroll
            for (int nt = 0; nt < 8; nt++)
                #pragma unroll
                for (int e = 0; e < 4; e++) s[nt][e] = 0.f;

            #pragma unroll
            for (int ks = 0; ks < 4; ks++) {
                uint32_t a0 = qf[mt][ks][0], a1 = qf[mt][ks][1];
                uint32_t a2 = qf[mt][ks][2], a3 = qf[mt][ks][3];
                #pragma unroll
                for (int nt = 0; nt < 8; nt++) {
                    int cn = nt*8 + rr;
                    uint32_t b0 = Kh[cn*KST + ks*8 + qq];
                    uint32_t b1 = Kh[cn*KST + ks*8 + qq + 4];
                    MMA_F16(s[nt], a0, a1, a2, a3, b0, b1);
                }
            }

            float rs_lo = 0.f, rs_hi = 0.f;
            #pragma unroll
            for (int nt = 0; nt < 8; nt++) {
                s[nt][0] = ex2(s[nt][0]);
                s[nt][1] = ex2(s[nt][1]);
                s[nt][2] = ex2(s[nt][2]);
                s[nt][3] = ex2(s[nt][3]);
                rs_lo += s[nt][0] + s[nt][1];
                rs_hi += s[nt][2] + s[nt][3];
                ph[mt][nt][0] = f22u(s[nt][0], s[nt][1]);
                ph[mt][nt][1] = f22u(s[nt][2], s[nt][3]);
            }
            #pragma unroll
            for (int off = 1; off <= 2; off <<= 1) {
                rs_lo += __shfl_xor_sync(0xffffffffu, rs_lo, off);
                rs_hi += __shfl_xor_sync(0xffffffffu, rs_hi, off);
            }
            l_i[mt][0] += rs_lo;
            l_i[mt][1] += rs_hi;
        }

        #pragma unroll
        for (int g = 0; g < 4; g++) {
            #pragma unroll
            for (int nt = 0; nt < 8; nt++) {
                int cn = nt*8 + rr;
                uint32_t b0 = Vt[cn*KST + g*8 + qq];
                uint32_t b1 = Vt[cn*KST + g*8 + qq + 4];
                MMA_F16(o[0][nt], ph[0][2*g][0], ph[0][2*g][1],
                                  ph[0][2*g+1][0], ph[0][2*g+1][1], b0, b1);
                MMA_F16(o[1][nt], ph[1][2*g][0], ph[1][2*g][1],
                                  ph[1][2*g+1][0], ph[1][2*g+1][1], b0, b1);
            }
        }
    }

    // Finalize -> fp16 gathered layout: row m = b*NN + n, col h*64 + d
    const int b = bh >> 4, h = bh & 15;
    #pragma unroll
    for (int mt = 0; mt < 2; mt++) {
        float inv_lo = 1.f / l_i[mt][0], inv_hi = 1.f / l_i[mt][1];
        int r_lo = q0 + w*32 + mt*16 + rr;
        int r_hi = r_lo + 8;
        uint32_t* po_lo = g_oh + (size_t)(b*NN + r_lo)*512 + h*32;
        uint32_t* po_hi = g_oh + (size_t)(b*NN + r_hi)*512 + h*32;
        #pragma unroll
        for (int nt = 0; nt < 8; nt++) {
            int cu = nt*4 + qq;        // u32 col within head
            po_lo[cu] = f22u(o[mt][nt][0]*inv_lo, o[mt][nt][1]*inv_lo);
            po_hi[cu] = f22u(o[mt][nt][2]*inv_hi, o[mt][nt][3]*inv_hi);
        }
    }
}

// ---------------------------------------------------------------------------
extern "C" void kernel_launch(void* const* d_in, const int* in_sizes, int n_in,
                              void* d_out, int out_size)
{
    const float* x   = (const float*)d_in[0];
    const float* rc  = (const float*)d_in[1];
    const float* rs  = (const float*)d_in[2];
    const float* Wq  = (const float*)d_in[3];
    const float* bq  = (const float*)d_in[4];
    const float* Wk  = (const float*)d_in[5];
    const float* bk  = (const float*)d_in[6];
    const float* Wv  = (const float*)d_in[7];
    const float* bv  = (const float*)d_in[8];
    const float* qnw = (const float*)d_in[9];
    const float* qnb = (const float*)d_in[10];
    const float* knw = (const float*)d_in[11];
    const float* knb = (const float*)d_in[12];
    const float* Wo  = (const float*)d_in[13];
    const float* bo  = (const float*)d_in[14];
    float* out = (float*)d_out;

    cudaFuncSetAttribute(mm_mma,
                         cudaFuncAttributeMaxDynamicSharedMemorySize, MM_SMEM);

    cvt_x<<<4096, 256>>>(x);
    cvt_w<<<2048, 256>>>(Wq, Wk, Wv, Wo);

    mm_mma<<<dim3(24, 32), 256, MM_SMEM>>>(0, bq, bk, bv, bo, out);

    const int warps2 = 2 * BB*HH*NN;           // q + k rows
    ln_rope<<<warps2/8, 256>>>(qnw, qnb, knw, knb, rc, rs);

    attn_mma<<<dim3(NN/128, BB*HH), 128>>>();

    mm_mma<<<dim3(8, 32), 256, MM_SMEM>>>(1, bq, bk, bv, bo, out);
}

// round 12
// speedup vs baseline: 7.1863x; 1.3575x over previous
#include <cuda_runtime.h>
#include <cuda_fp16.h>
#include <cstdint>

#define BB   2
#define NN   2048
#define DIMC 1024
#define HH   16
#define HD   64

// Scratch (allocation-free requirement)
__device__ float    g_q[BB*HH*NN*HD];       // fp32 q after projection
__device__ float    g_k[BB*HH*NN*HD];       // fp32 k after projection
__device__ uint32_t g_qh[BB*HH*NN*HD/2];    // q post-LN/RoPE, half2, QS-scaled
__device__ uint32_t g_kh[BB*HH*NN*HD/2];    // k post-LN/RoPE, half2
__device__ uint32_t g_vh[BB*HH*NN*HD/2];    // v half2 (packed in mm epilogue)
__device__ uint32_t g_xh[BB*NN*DIMC/2];     // x as half2 pairs  [4096][512]
__device__ uint32_t g_oh[BB*NN*DIMC/2];     // attn out as half2 [4096][512]
__device__ uint32_t g_wh[4*(DIMC/2)*DIMC];  // W{q,k,v,o} kpair-packed half2

// ---------------------------------------------------------------------------
__device__ __forceinline__ uint32_t f22u(float a, float b) {
    __half2 h = __floats2half2_rn(a, b);
    return *(uint32_t*)&h;
}
__device__ __forceinline__ float ex2(float x) {
    float y;
    asm("ex2.approx.f32 %0, %1;" : "=f"(y) : "f"(x));
    return y;
}
__device__ __forceinline__ void cp16(void* dst, const void* src) {
    uint32_t sa = (uint32_t)__cvta_generic_to_shared(dst);
    asm volatile("cp.async.cg.shared.global [%0], [%1], 16;"
                 :: "r"(sa), "l"(src));
}
#define CP_COMMIT() asm volatile("cp.async.commit_group;")
#define CP_WAIT(n)  asm volatile("cp.async.wait_group %0;" :: "n"(n))

#define MMA_F16(c, a0, a1, a2, a3, b0, b1)                                    \
    asm volatile(                                                             \
        "mma.sync.aligned.m16n8k16.row.col.f32.f16.f16.f32 "                  \
        "{%0,%1,%2,%3}, {%4,%5,%6,%7}, {%8,%9}, {%0,%1,%2,%3};"               \
        : "+f"((c)[0]), "+f"((c)[1]), "+f"((c)[2]), "+f"((c)[3])              \
        : "r"(a0), "r"(a1), "r"(a2), "r"(a3), "r"(b0), "r"(b1))

#define LDSM_X4_T(b, addr)                                                    \
    asm volatile(                                                             \
        "ldmatrix.sync.aligned.m8n8.x4.trans.shared.b16 {%0,%1,%2,%3}, [%4];" \
        : "=r"((b)[0]), "=r"((b)[1]), "=r"((b)[2]), "=r"((b)[3])              \
        : "r"(addr))

// ---------------------------------------------------------------------------
__global__ __launch_bounds__(256) void cvt_x(const float* __restrict__ x)
{
    int i = blockIdx.x * blockDim.x + threadIdx.x;     // 0..1048575
    float4 v = ((const float4*)x)[i];
    ((uint2*)g_xh)[i] = make_uint2(f22u(v.x, v.y), f22u(v.z, v.w));
}

__global__ __launch_bounds__(256) void cvt_w(
    const float* __restrict__ Wq, const float* __restrict__ Wk,
    const float* __restrict__ Wv, const float* __restrict__ Wo)
{
    int idx = blockIdx.x * blockDim.x + threadIdx.x;   // 0..524287
    int mat = idx >> 17;
    int kp  = (idx >> 8) & 511;
    int c4  = idx & 255;
    const float* W = (mat == 0) ? Wq : (mat == 1) ? Wk : (mat == 2) ? Wv : Wo;
    const float4 r0 = *(const float4*)(W + (size_t)(2*kp  )*DIMC + c4*4);
    const float4 r1 = *(const float4*)(W + (size_t)(2*kp+1)*DIMC + c4*4);
    uint4 o;
    o.x = f22u(r0.x, r1.x); o.y = f22u(r0.y, r1.y);
    o.z = f22u(r0.z, r1.z); o.w = f22u(r0.w, r1.w);
    *(uint4*)&g_wh[((size_t)mat*512 + kp)*DIMC + c4*4] = o;
}

// ---------------------------------------------------------------------------
// fp16 m16n8k16 GEMM, 3-stage cp.async pipeline (unchanged from R10).
// ---------------------------------------------------------------------------
#define MMW 20
#define BWW 136
#define ASZ (128*MMW)
#define BSZ (16*BWW)
#define MM_SMEM (3*(ASZ+BSZ)*4)   // 56832 B

__global__ __launch_bounds__(256, 2) void mm_mma(
    int mode,
    const float* __restrict__ bq, const float* __restrict__ bk,
    const float* __restrict__ bv, const float* __restrict__ bo,
    float* __restrict__ out)
{
    extern __shared__ __align__(16) uint32_t dsm[];
    uint32_t* As = dsm;
    uint32_t* Bs = dsm + 3*ASZ;

    const int tid = threadIdx.x, lane = tid & 31, w = tid >> 5;
    const int wm = w & 3, wn = w >> 2;
    const int rr = lane >> 2, qq = lane & 3;
    const int m0 = blockIdx.y * 128, c0 = blockIdx.x * 128;

    const uint32_t* Asrc = mode ? g_oh : g_xh;
    int mat, j0;
    if (mode == 1) { mat = 3; j0 = c0; }
    else           { mat = c0 >> 10; j0 = c0 & 1023; }
    const uint32_t* Bsrc = g_wh + (size_t)mat * 512 * DIMC;

    const int ra0 = tid >> 2,       ca0 = tid & 3;
    const int ra1 = (tid+256) >> 2, ca1 = (tid+256) & 3;
    const int kb0 = tid >> 5,       cb0 = tid & 31;
    const int kb1 = (tid+256) >> 5, cb1 = (tid+256) & 31;

    auto issue = [&](int kc, int s) {
        const int kp0 = kc * 16;
        cp16(&As[s*ASZ + ra0*MMW + ca0*4],
             Asrc + (size_t)(m0 + ra0)*512 + kp0 + ca0*4);
        cp16(&As[s*ASZ + ra1*MMW + ca1*4],
             Asrc + (size_t)(m0 + ra1)*512 + kp0 + ca1*4);
        cp16(&Bs[s*BSZ + kb0*BWW + cb0*4],
             Bsrc + (size_t)(kp0 + kb0)*DIMC + j0 + cb0*4);
        cp16(&Bs[s*BSZ + kb1*BWW + cb1*4],
             Bsrc + (size_t)(kp0 + kb1)*DIMC + j0 + cb1*4);
        CP_COMMIT();
    };

    float acc[2][8][4];
    #pragma unroll
    for (int mt = 0; mt < 2; mt++)
        #pragma unroll
        for (int nt = 0; nt < 8; nt++)
            #pragma unroll
            for (int e = 0; e < 4; e++) acc[mt][nt][e] = 0.f;

    issue(0, 0);
    issue(1, 1);

    for (int kc = 0; kc < DIMC/32; kc++) {
        if (kc < DIMC/32 - 2) { CP_WAIT(1); } else { CP_WAIT(0); }
        __syncthreads();

        const uint32_t* Ac = &As[(kc % 3)*ASZ];
        const uint32_t* Bc = &Bs[(kc % 3)*BSZ];
        #pragma unroll
        for (int ks = 0; ks < 2; ks++) {
            const int ku = ks * 8 + qq;
            uint32_t a[2][4];
            #pragma unroll
            for (int mt = 0; mt < 2; mt++) {
                int rm = wm*32 + mt*16 + rr;
                a[mt][0] = Ac[rm*MMW     + ku];
                a[mt][1] = Ac[(rm+8)*MMW + ku];
                a[mt][2] = Ac[rm*MMW     + ku + 4];
                a[mt][3] = Ac[(rm+8)*MMW + ku + 4];
            }
            #pragma unroll
            for (int nt = 0; nt < 8; nt++) {
                int cn = wn*64 + nt*8 + rr;
                uint32_t b0 = Bc[(ks*8 + qq)*BWW     + cn];
                uint32_t b1 = Bc[(ks*8 + qq + 4)*BWW + cn];
                MMA_F16(acc[0][nt], a[0][0], a[0][1], a[0][2], a[0][3], b0, b1);
                MMA_F16(acc[1][nt], a[1][0], a[1][1], a[1][2], a[1][3], b0, b1);
            }
        }

        if (kc + 2 < DIMC/32) issue(kc + 2, (kc + 2) % 3);
    }

    // Epilogue.  mode 0: q,k scatter as fp32; v packed half2 -> g_vh.
    #pragma unroll
    for (int mt = 0; mt < 2; mt++) {
        int r_lo = m0 + wm*32 + mt*16 + rr;
        int r_hi = r_lo + 8;
        #pragma unroll
        for (int nt = 0; nt < 8; nt++) {
            int c = c0 + wn*64 + nt*8 + qq*2;
            if (mode == 0) {
                int t = c % 192, h = c / 192, d = t & 63;
                int bz_lo = r_lo >> 11, n_lo = r_lo & (NN-1);
                int bz_hi = r_hi >> 11, n_hi = r_hi & (NN-1);
                if (t < 128) {
                    float bias0, bias1;
                    float* dst;
                    if (t < 64) { bias0 = bq[c];      bias1 = bq[c+1];      dst = g_q; }
                    else        { bias0 = bk[c-DIMC]; bias1 = bk[c-DIMC+1]; dst = g_k; }
                    size_t lo = (((size_t)bz_lo*HH + h)*NN + n_lo)*HD + d;
                    size_t hi = (((size_t)bz_hi*HH + h)*NN + n_hi)*HD + d;
                    dst[lo]   = acc[mt][nt][0] + bias0;
                    dst[lo+1] = acc[mt][nt][1] + bias1;
                    dst[hi]   = acc[mt][nt][2] + bias0;
                    dst[hi+1] = acc[mt][nt][3] + bias1;
                } else {
                    float bias0 = bv[c - 2*DIMC], bias1 = bv[c - 2*DIMC + 1];
                    g_vh[(((size_t)bz_lo*HH + h)*NN + n_lo)*32 + (d>>1)] =
                        f22u(acc[mt][nt][0] + bias0, acc[mt][nt][1] + bias1);
                    g_vh[(((size_t)bz_hi*HH + h)*NN + n_hi)*32 + (d>>1)] =
                        f22u(acc[mt][nt][2] + bias0, acc[mt][nt][3] + bias1);
                }
            } else {
                float2 lo = make_float2(acc[mt][nt][0] + bo[c],
                                        acc[mt][nt][1] + bo[c+1]);
                float2 hi = make_float2(acc[mt][nt][2] + bo[c],
                                        acc[mt][nt][3] + bo[c+1]);
                *(float2*)(out + (size_t)r_lo*DIMC + c) = lo;
                *(float2*)(out + (size_t)r_hi*DIMC + c) = hi;
            }
        }
    }
}

// ---------------------------------------------------------------------------
// LayerNorm + RoPE v2: lane owns adjacent pair (2l, 2l+1); rotate partner via
// shfl_xor(16).  Outputs packed half2: q (QS-prescaled) -> g_qh, k -> g_kh.
// ---------------------------------------------------------------------------
__global__ __launch_bounds__(256) void ln_rope(
    const float* __restrict__ qnw, const float* __restrict__ qnb,
    const float* __restrict__ knw, const float* __restrict__ knb,
    const float* __restrict__ cosb, const float* __restrict__ sinb)
{
    const int R = BB*HH*NN;
    const float QS = 0.125f * 1.4426950408889634f;
    int warp = (blockIdx.x * blockDim.x + threadIdx.x) >> 5;
    int lane = threadIdx.x & 31;
    int which = warp >= R;
    int wr = warp - (which ? R : 0);
    int bz = wr / (HH*NN);
    int n  = wr & (NN-1);

    const float* nw = which ? knw : qnw;
    const float* nb = which ? knb : qnb;
    const float* src = (which ? g_k : g_q) + (size_t)wr * HD;

    float2 xv = *(const float2*)(src + 2*lane);
    float sum = xv.x + xv.y;
    float sq  = xv.x*xv.x + xv.y*xv.y;
    #pragma unroll
    for (int o = 16; o; o >>= 1) {
        sum += __shfl_xor_sync(0xffffffffu, sum, o);
        sq  += __shfl_xor_sync(0xffffffffu, sq,  o);
    }
    float mean = sum * (1.f/64.f);
    float var  = sq  * (1.f/64.f) - mean*mean;
    float inv  = rsqrtf(var + 1e-6f);
    float2 wv = *(const float2*)(nw + 2*lane);
    float2 bvv = *(const float2*)(nb + 2*lane);
    float y0 = (xv.x - mean) * inv * wv.x + bvv.x;
    float y1 = (xv.y - mean) * inv * wv.y + bvv.y;

    float p0 = __shfl_xor_sync(0xffffffffu, y0, 16);
    float p1 = __shfl_xor_sync(0xffffffffu, y1, 16);
    float sgn = (lane < 16) ? -1.f : 1.f;

    size_t rbase = ((size_t)bz*NN + n) * HD;
    float2 cv = *(const float2*)(cosb + rbase + 2*lane);
    float2 sv = *(const float2*)(sinb + rbase + 2*lane);
    float o0 = y0*cv.x + sgn*p0*sv.x;
    float o1 = y1*cv.y + sgn*p1*sv.y;

    if (!which) g_qh[(size_t)wr*32 + lane] = f22u(o0*QS, o1*QS);
    else        g_kh[(size_t)wr*32 + lane] = f22u(o0, o1);
}

// ---------------------------------------------------------------------------
// Flash attention v5: all-fp16 sources, cp.async double-buffered K/V staging
// (zero staging ALU), PV B-frags via ldmatrix.x4.trans (no V transpose).
// 128 threads / 4 warps; q-tile 128; k-tile 64; no-max softmax; P in regs.
// ---------------------------------------------------------------------------
#define KST 36      // u32 stride for Kh / Vh rows (144 B: LDSM conflict-free)

__global__ __launch_bounds__(128) void attn_mma()
{
    __shared__ __align__(16) uint32_t Kh[2][64*KST];
    __shared__ __align__(16) uint32_t Vh[2][64*KST];

    const int tid = threadIdx.x, lane = tid & 31, w = tid >> 5;   // w: 0..3
    const int bh = blockIdx.y;
    const int q0 = blockIdx.x * 128;
    const uint32_t* qh = g_qh + (size_t)bh * NN * 32;
    const uint32_t* kh = g_kh + (size_t)bh * NN * 32;
    const uint32_t* vh = g_vh + (size_t)bh * NN * 32;

    const int rr = lane >> 2;       // 0..7
    const int qq = lane & 3;

    // Q A-fragments: direct u32 loads (already fp16, pre-scaled)
    uint32_t qf[2][4][4];
    #pragma unroll
    for (int mt = 0; mt < 2; mt++) {
        int rbase = q0 + w*32 + mt*16 + rr;
        #pragma unroll
        for (int ks = 0; ks < 4; ks++) {
            qf[mt][ks][0] = qh[(size_t)rbase*32     + ks*8 + qq];
            qf[mt][ks][1] = qh[(size_t)(rbase+8)*32 + ks*8 + qq];
            qf[mt][ks][2] = qh[(size_t)rbase*32     + ks*8 + qq + 4];
            qf[mt][ks][3] = qh[(size_t)(rbase+8)*32 + ks*8 + qq + 4];
        }
    }

    // ldmatrix lane offset (u32): row = lane&15, +4 u32 cols for lanes 16-31
    const int lm_base = (lane & 15)*KST + (lane >> 4)*4;

    auto issue = [&](int kt, int s) {
        const int k0 = kt * 64;
        #pragma unroll
        for (int i = 0; i < 4; i++) {
            int idx = tid + i*128;      // 0..511: r = idx>>3, c4 = idx&7
            int r = idx >> 3, c4 = idx & 7;
            cp16(&Kh[s][r*KST + c4*4], kh + (size_t)(k0 + r)*32 + c4*4);
            cp16(&Vh[s][r*KST + c4*4], vh + (size_t)(k0 + r)*32 + c4*4);
        }
        CP_COMMIT();
    };

    float l_i[2][2];
    float o[2][8][4];
    #pragma unroll
    for (int mt = 0; mt < 2; mt++) {
        l_i[mt][0] = 0.f; l_i[mt][1] = 0.f;
        #pragma unroll
        for (int nt = 0; nt < 8; nt++)
            #pragma unroll
            for (int e = 0; e < 4; e++) o[mt][nt][e] = 0.f;
    }

    issue(0, 0);

    for (int kt = 0; kt < NN/64; kt++) {
        const int s = kt & 1;
        CP_WAIT(0);
        __syncthreads();                 // publish tile kt; close compute kt-1
        if (kt + 1 < NN/64) issue(kt + 1, s ^ 1);   // overlaps with compute

        uint32_t ph[2][8][2];

        #pragma unroll
        for (int mt = 0; mt < 2; mt++) {
            float sc[8][4];
            #pragma unroll
            for (int nt = 0; nt < 8; nt++)
                #pragma unroll
                for (int e = 0; e < 4; e++) sc[nt][e] = 0.f;

            #pragma unroll
            for (int ks = 0; ks < 4; ks++) {
                uint32_t a0 = qf[mt][ks][0], a1 = qf[mt][ks][1];
                uint32_t a2 = qf[mt][ks][2], a3 = qf[mt][ks][3];
                #pragma unroll
                for (int nt = 0; nt < 8; nt++) {
                    int cn = nt*8 + rr;
                    uint32_t b0 = Kh[s][cn*KST + ks*8 + qq];
                    uint32_t b1 = Kh[s][cn*KST + ks*8 + qq + 4];
                    MMA_F16(sc[nt], a0, a1, a2, a3, b0, b1);
                }
            }

            float rs_lo = 0.f, rs_hi = 0.f;
            #pragma unroll
            for (int nt = 0; nt < 8; nt++) {
                sc[nt][0] = ex2(sc[nt][0]);
                sc[nt][1] = ex2(sc[nt][1]);
                sc[nt][2] = ex2(sc[nt][2]);
                sc[nt][3] = ex2(sc[nt][3]);
                rs_lo += sc[nt][0] + sc[nt][1];
                rs_hi += sc[nt][2] + sc[nt][3];
                ph[mt][nt][0] = f22u(sc[nt][0], sc[nt][1]);
                ph[mt][nt][1] = f22u(sc[nt][2], sc[nt][3]);
            }
            #pragma unroll
            for (int off = 1; off <= 2; off <<= 1) {
                rs_lo += __shfl_xor_sync(0xffffffffu, rs_lo, off);
                rs_hi += __shfl_xor_sync(0xffffffffu, rs_hi, off);
            }
            l_i[mt][0] += rs_lo;
            l_i[mt][1] += rs_hi;
        }

        // O += P @ V: B-frags via ldmatrix.trans on row-major Vh tile
        #pragma unroll
        for (int g = 0; g < 4; g++) {
            #pragma unroll
            for (int ntp = 0; ntp < 4; ntp++) {
                uint32_t b[4];
                uint32_t addr = (uint32_t)__cvta_generic_to_shared(
                    &Vh[s][g*16*KST + ntp*8 + lm_base]);
                LDSM_X4_T(b, addr);
                MMA_F16(o[0][2*ntp],   ph[0][2*g][0], ph[0][2*g][1],
                                       ph[0][2*g+1][0], ph[0][2*g+1][1], b[0], b[1]);
                MMA_F16(o[1][2*ntp],   ph[1][2*g][0], ph[1][2*g][1],
                                       ph[1][2*g+1][0], ph[1][2*g+1][1], b[0], b[1]);
                MMA_F16(o[0][2*ntp+1], ph[0][2*g][0], ph[0][2*g][1],
                                       ph[0][2*g+1][0], ph[0][2*g+1][1], b[2], b[3]);
                MMA_F16(o[1][2*ntp+1], ph[1][2*g][0], ph[1][2*g][1],
                                       ph[1][2*g+1][0], ph[1][2*g+1][1], b[2], b[3]);
            }
        }
    }

    // Finalize -> fp16 gathered layout: row m = b*NN + n, col h*64 + d
    const int b = bh >> 4, h = bh & 15;
    #pragma unroll
    for (int mt = 0; mt < 2; mt++) {
        float inv_lo = 1.f / l_i[mt][0], inv_hi = 1.f / l_i[mt][1];
        int r_lo = q0 + w*32 + mt*16 + rr;
        int r_hi = r_lo + 8;
        uint32_t* po_lo = g_oh + (size_t)(b*NN + r_lo)*512 + h*32;
        uint32_t* po_hi = g_oh + (size_t)(b*NN + r_hi)*512 + h*32;
        #pragma unroll
        for (int nt = 0; nt < 8; nt++) {
            int cu = nt*4 + qq;
            po_lo[cu] = f22u(o[mt][nt][0]*inv_lo, o[mt][nt][1]*inv_lo);
            po_hi[cu] = f22u(o[mt][nt][2]*inv_hi, o[mt][nt][3]*inv_hi);
        }
    }
}

// ---------------------------------------------------------------------------
extern "C" void kernel_launch(void* const* d_in, const int* in_sizes, int n_in,
                              void* d_out, int out_size)
{
    const float* x   = (const float*)d_in[0];
    const float* rc  = (const float*)d_in[1];
    const float* rs  = (const float*)d_in[2];
    const float* Wq  = (const float*)d_in[3];
    const float* bq  = (const float*)d_in[4];
    const float* Wk  = (const float*)d_in[5];
    const float* bk  = (const float*)d_in[6];
    const float* Wv  = (const float*)d_in[7];
    const float* bv  = (const float*)d_in[8];
    const float* qnw = (const float*)d_in[9];
    const float* qnb = (const float*)d_in[10];
    const float* knw = (const float*)d_in[11];
    const float* knb = (const float*)d_in[12];
    const float* Wo  = (const float*)d_in[13];
    const float* bo  = (const float*)d_in[14];
    float* out = (float*)d_out;

    cudaFuncSetAttribute(mm_mma,
                         cudaFuncAttributeMaxDynamicSharedMemorySize, MM_SMEM);

    cvt_x<<<4096, 256>>>(x);
    cvt_w<<<2048, 256>>>(Wq, Wk, Wv, Wo);

    mm_mma<<<dim3(24, 32), 256, MM_SMEM>>>(0, bq, bk, bv, bo, out);

    const int warps2 = 2 * BB*HH*NN;           // q + k rows
    ln_rope<<<warps2/8, 256>>>(qnw, qnb, knw, knb, rc, rs);

    attn_mma<<<dim3(NN/128, BB*HH), 128>>>();

    mm_mma<<<dim3(8, 32), 256, MM_SMEM>>>(1, bq, bk, bv, bo, out);
}

// round 13
// speedup vs baseline: 7.5462x; 1.0501x over previous
#include <cuda_runtime.h>
#include <cuda_fp16.h>
#include <cstdint>

#define BB   2
#define NN   2048
#define DIMC 1024
#define HH   16
#define HD   64

// Scratch (allocation-free requirement)
__device__ float    g_q[BB*HH*NN*HD];       // fp32 q after projection
__device__ float    g_k[BB*HH*NN*HD];       // fp32 k after projection
__device__ uint32_t g_qh[BB*HH*NN*HD/2];    // q post-LN/RoPE, half2, QS-scaled
__device__ uint32_t g_kh[BB*HH*NN*HD/2];    // k post-LN/RoPE, half2
__device__ uint32_t g_vh[BB*HH*NN*HD/2];    // v half2 (packed in mm epilogue)
__device__ uint32_t g_xh[BB*NN*DIMC/2];     // x as half2 pairs  [4096][512]
__device__ uint32_t g_oh[BB*NN*DIMC/2];     // attn out as half2 [4096][512]
__device__ uint32_t g_wh[4*(DIMC/2)*DIMC];  // W{q,k,v,o} kpair-packed half2

// ---------------------------------------------------------------------------
__device__ __forceinline__ uint32_t f22u(float a, float b) {
    __half2 h = __floats2half2_rn(a, b);
    return *(uint32_t*)&h;
}
__device__ __forceinline__ float ex2(float x) {
    float y;
    asm("ex2.approx.f32 %0, %1;" : "=f"(y) : "f"(x));
    return y;
}
__device__ __forceinline__ void cp16(void* dst, const void* src) {
    uint32_t sa = (uint32_t)__cvta_generic_to_shared(dst);
    asm volatile("cp.async.cg.shared.global [%0], [%1], 16;"
                 :: "r"(sa), "l"(src));
}
#define CP_COMMIT() asm volatile("cp.async.commit_group;")
#define CP_WAIT(n)  asm volatile("cp.async.wait_group %0;" :: "n"(n))

#define MMA_F16(c, a0, a1, a2, a3, b0, b1)                                    \
    asm volatile(                                                             \
        "mma.sync.aligned.m16n8k16.row.col.f32.f16.f16.f32 "                  \
        "{%0,%1,%2,%3}, {%4,%5,%6,%7}, {%8,%9}, {%0,%1,%2,%3};"               \
        : "+f"((c)[0]), "+f"((c)[1]), "+f"((c)[2]), "+f"((c)[3])              \
        : "r"(a0), "r"(a1), "r"(a2), "r"(a3), "r"(b0), "r"(b1))

#define LDSM_X4_T(b, addr)                                                    \
    asm volatile(                                                             \
        "ldmatrix.sync.aligned.m8n8.x4.trans.shared.b16 {%0,%1,%2,%3}, [%4];" \
        : "=r"((b)[0]), "=r"((b)[1]), "=r"((b)[2]), "=r"((b)[3])              \
        : "r"(addr))

// ---------------------------------------------------------------------------
// Fused fp16 conversion: blocks [0,4096) convert x; [4096, 6144) convert W.
// ---------------------------------------------------------------------------
__global__ __launch_bounds__(256) void cvt_all(
    const float* __restrict__ x,
    const float* __restrict__ Wq, const float* __restrict__ Wk,
    const float* __restrict__ Wv, const float* __restrict__ Wo)
{
    if (blockIdx.x < 4096) {
        int i = blockIdx.x * 256 + threadIdx.x;        // 0..1048575
        float4 v = ((const float4*)x)[i];
        ((uint2*)g_xh)[i] = make_uint2(f22u(v.x, v.y), f22u(v.z, v.w));
    } else {
        int idx = (blockIdx.x - 4096) * 256 + threadIdx.x;   // 0..524287
        int mat = idx >> 17;
        int kp  = (idx >> 8) & 511;
        int c4  = idx & 255;
        const float* W = (mat == 0) ? Wq : (mat == 1) ? Wk
                       : (mat == 2) ? Wv : Wo;
        const float4 r0 = *(const float4*)(W + (size_t)(2*kp  )*DIMC + c4*4);
        const float4 r1 = *(const float4*)(W + (size_t)(2*kp+1)*DIMC + c4*4);
        uint4 o;
        o.x = f22u(r0.x, r1.x); o.y = f22u(r0.y, r1.y);
        o.z = f22u(r0.z, r1.z); o.w = f22u(r0.w, r1.w);
        *(uint4*)&g_wh[((size_t)mat*512 + kp)*DIMC + c4*4] = o;
    }
}

// ---------------------------------------------------------------------------
// fp16 m16n8k16 GEMM, 3-stage cp.async pipeline (unchanged from R11).
// ---------------------------------------------------------------------------
#define MMW 20
#define BWW 136
#define ASZ (128*MMW)
#define BSZ (16*BWW)
#define MM_SMEM (3*(ASZ+BSZ)*4)   // 56832 B

__global__ __launch_bounds__(256, 2) void mm_mma(
    int mode,
    const float* __restrict__ bq, const float* __restrict__ bk,
    const float* __restrict__ bv, const float* __restrict__ bo,
    float* __restrict__ out)
{
    extern __shared__ __align__(16) uint32_t dsm[];
    uint32_t* As = dsm;
    uint32_t* Bs = dsm + 3*ASZ;

    const int tid = threadIdx.x, lane = tid & 31, w = tid >> 5;
    const int wm = w & 3, wn = w >> 2;
    const int rr = lane >> 2, qq = lane & 3;
    const int m0 = blockIdx.y * 128, c0 = blockIdx.x * 128;

    const uint32_t* Asrc = mode ? g_oh : g_xh;
    int mat, j0;
    if (mode == 1) { mat = 3; j0 = c0; }
    else           { mat = c0 >> 10; j0 = c0 & 1023; }
    const uint32_t* Bsrc = g_wh + (size_t)mat * 512 * DIMC;

    const int ra0 = tid >> 2,       ca0 = tid & 3;
    const int ra1 = (tid+256) >> 2, ca1 = (tid+256) & 3;
    const int kb0 = tid >> 5,       cb0 = tid & 31;
    const int kb1 = (tid+256) >> 5, cb1 = (tid+256) & 31;

    auto issue = [&](int kc, int s) {
        const int kp0 = kc * 16;
        cp16(&As[s*ASZ + ra0*MMW + ca0*4],
             Asrc + (size_t)(m0 + ra0)*512 + kp0 + ca0*4);
        cp16(&As[s*ASZ + ra1*MMW + ca1*4],
             Asrc + (size_t)(m0 + ra1)*512 + kp0 + ca1*4);
        cp16(&Bs[s*BSZ + kb0*BWW + cb0*4],
             Bsrc + (size_t)(kp0 + kb0)*DIMC + j0 + cb0*4);
        cp16(&Bs[s*BSZ + kb1*BWW + cb1*4],
             Bsrc + (size_t)(kp0 + kb1)*DIMC + j0 + cb1*4);
        CP_COMMIT();
    };

    float acc[2][8][4];
    #pragma unroll
    for (int mt = 0; mt < 2; mt++)
        #pragma unroll
        for (int nt = 0; nt < 8; nt++)
            #pragma unroll
            for (int e = 0; e < 4; e++) acc[mt][nt][e] = 0.f;

    issue(0, 0);
    issue(1, 1);

    for (int kc = 0; kc < DIMC/32; kc++) {
        if (kc < DIMC/32 - 2) { CP_WAIT(1); } else { CP_WAIT(0); }
        __syncthreads();

        const uint32_t* Ac = &As[(kc % 3)*ASZ];
        const uint32_t* Bc = &Bs[(kc % 3)*BSZ];
        #pragma unroll
        for (int ks = 0; ks < 2; ks++) {
            const int ku = ks * 8 + qq;
            uint32_t a[2][4];
            #pragma unroll
            for (int mt = 0; mt < 2; mt++) {
                int rm = wm*32 + mt*16 + rr;
                a[mt][0] = Ac[rm*MMW     + ku];
                a[mt][1] = Ac[(rm+8)*MMW + ku];
                a[mt][2] = Ac[rm*MMW     + ku + 4];
                a[mt][3] = Ac[(rm+8)*MMW + ku + 4];
            }
            #pragma unroll
            for (int nt = 0; nt < 8; nt++) {
                int cn = wn*64 + nt*8 + rr;
                uint32_t b0 = Bc[(ks*8 + qq)*BWW     + cn];
                uint32_t b1 = Bc[(ks*8 + qq + 4)*BWW + cn];
                MMA_F16(acc[0][nt], a[0][0], a[0][1], a[0][2], a[0][3], b0, b1);
                MMA_F16(acc[1][nt], a[1][0], a[1][1], a[1][2], a[1][3], b0, b1);
            }
        }

        if (kc + 2 < DIMC/32) issue(kc + 2, (kc + 2) % 3);
    }

    // Epilogue.  mode 0: q,k scatter as fp32; v packed half2 -> g_vh.
    #pragma unroll
    for (int mt = 0; mt < 2; mt++) {
        int r_lo = m0 + wm*32 + mt*16 + rr;
        int r_hi = r_lo + 8;
        #pragma unroll
        for (int nt = 0; nt < 8; nt++) {
            int c = c0 + wn*64 + nt*8 + qq*2;
            if (mode == 0) {
                int t = c % 192, h = c / 192, d = t & 63;
                int bz_lo = r_lo >> 11, n_lo = r_lo & (NN-1);
                int bz_hi = r_hi >> 11, n_hi = r_hi & (NN-1);
                if (t < 128) {
                    float bias0, bias1;
                    float* dst;
                    if (t < 64) { bias0 = bq[c];      bias1 = bq[c+1];      dst = g_q; }
                    else        { bias0 = bk[c-DIMC]; bias1 = bk[c-DIMC+1]; dst = g_k; }
                    size_t lo = (((size_t)bz_lo*HH + h)*NN + n_lo)*HD + d;
                    size_t hi = (((size_t)bz_hi*HH + h)*NN + n_hi)*HD + d;
                    dst[lo]   = acc[mt][nt][0] + bias0;
                    dst[lo+1] = acc[mt][nt][1] + bias1;
                    dst[hi]   = acc[mt][nt][2] + bias0;
                    dst[hi+1] = acc[mt][nt][3] + bias1;
                } else {
                    float bias0 = bv[c - 2*DIMC], bias1 = bv[c - 2*DIMC + 1];
                    g_vh[(((size_t)bz_lo*HH + h)*NN + n_lo)*32 + (d>>1)] =
                        f22u(acc[mt][nt][0] + bias0, acc[mt][nt][1] + bias1);
                    g_vh[(((size_t)bz_hi*HH + h)*NN + n_hi)*32 + (d>>1)] =
                        f22u(acc[mt][nt][2] + bias0, acc[mt][nt][3] + bias1);
                }
            } else {
                float2 lo = make_float2(acc[mt][nt][0] + bo[c],
                                        acc[mt][nt][1] + bo[c+1]);
                float2 hi = make_float2(acc[mt][nt][2] + bo[c],
                                        acc[mt][nt][3] + bo[c+1]);
                *(float2*)(out + (size_t)r_lo*DIMC + c) = lo;
                *(float2*)(out + (size_t)r_hi*DIMC + c) = hi;
            }
        }
    }
}

// ---------------------------------------------------------------------------
// LayerNorm + RoPE v3: HALF-warp per row (16 lanes x 4 elems), 2 rows/warp.
// Reductions via xor 1/2/4/8 (stay within each 16-lane group); RoPE partner
// (d +/- 32) via xor 8 with sign from lane&8.  Same fp32 math/rounding.
// ---------------------------------------------------------------------------
__global__ __launch_bounds__(256) void ln_rope(
    const float* __restrict__ qnw, const float* __restrict__ qnb,
    const float* __restrict__ knw, const float* __restrict__ knb,
    const float* __restrict__ cosb, const float* __restrict__ sinb)
{
    const int R = BB*HH*NN;
    const float QS = 0.125f * 1.4426950408889634f;
    int warp = (blockIdx.x * blockDim.x + threadIdx.x) >> 5;
    int lane = threadIdx.x & 31;
    int hw   = lane >> 4;               // half-warp id (0/1)
    int hl   = lane & 15;               // lane within half-warp
    int r    = 2*warp + hw;             // global row id (q rows then k rows)
    int which = r >= R;
    int wr = r - (which ? R : 0);
    int bz = wr / (HH*NN);
    int n  = wr & (NN-1);

    const float* nw = which ? knw : qnw;
    const float* nb = which ? knb : qnb;
    const float* src = (which ? g_k : g_q) + (size_t)wr * HD;

    float4 xv = *(const float4*)(src + 4*hl);
    float sum = (xv.x + xv.y) + (xv.z + xv.w);
    float sq  = xv.x*xv.x + xv.y*xv.y + xv.z*xv.z + xv.w*xv.w;
    #pragma unroll
    for (int o = 8; o; o >>= 1) {
        sum += __shfl_xor_sync(0xffffffffu, sum, o);
        sq  += __shfl_xor_sync(0xffffffffu, sq,  o);
    }
    float mean = sum * (1.f/64.f);
    float var  = sq  * (1.f/64.f) - mean*mean;
    float inv  = rsqrtf(var + 1e-6f);
    float4 wv  = *(const float4*)(nw + 4*hl);
    float4 bvv = *(const float4*)(nb + 4*hl);
    float y0 = (xv.x - mean) * inv * wv.x + bvv.x;
    float y1 = (xv.y - mean) * inv * wv.y + bvv.y;
    float y2 = (xv.z - mean) * inv * wv.z + bvv.z;
    float y3 = (xv.w - mean) * inv * wv.w + bvv.w;

    // rotate_half partner: d<32 -> -x[d+32] (lane+8); d>=32 -> +x[d-32]
    float p0 = __shfl_xor_sync(0xffffffffu, y0, 8);
    float p1 = __shfl_xor_sync(0xffffffffu, y1, 8);
    float p2 = __shfl_xor_sync(0xffffffffu, y2, 8);
    float p3 = __shfl_xor_sync(0xffffffffu, y3, 8);
    float sgn = (hl & 8) ? 1.f : -1.f;

    size_t rbase = ((size_t)bz*NN + n) * HD;
    float4 cv = *(const float4*)(cosb + rbase + 4*hl);
    float4 sv = *(const float4*)(sinb + rbase + 4*hl);
    float o0 = y0*cv.x + sgn*p0*sv.x;
    float o1 = y1*cv.y + sgn*p1*sv.y;
    float o2 = y2*cv.z + sgn*p2*sv.z;
    float o3 = y3*cv.w + sgn*p3*sv.w;

    uint2 pk;
    if (!which) { pk = make_uint2(f22u(o0*QS, o1*QS), f22u(o2*QS, o3*QS)); }
    else        { pk = make_uint2(f22u(o0, o1),       f22u(o2, o3)); }
    *(uint2*)&((which ? g_kh : g_qh)[(size_t)wr*32 + 2*hl]) = pk;
}

// ---------------------------------------------------------------------------
// Flash attention v6: K B-frags hoisted across both m-tiles (S for both mt
// accumulated in one k-loop -> 64 LDS/tile instead of 128).  Otherwise v5:
// all-fp16, cp.async double buffer, ldmatrix.trans for PV, no-max softmax.
// ---------------------------------------------------------------------------
#define KST 36      // u32 stride for Kh / Vh rows (144 B)

__global__ __launch_bounds__(128, 2) void attn_mma()
{
    __shared__ __align__(16) uint32_t Kh[2][64*KST];
    __shared__ __align__(16) uint32_t Vh[2][64*KST];

    const int tid = threadIdx.x, lane = tid & 31, w = tid >> 5;   // w: 0..3
    const int bh = blockIdx.y;
    const int q0 = blockIdx.x * 128;
    const uint32_t* qh = g_qh + (size_t)bh * NN * 32;
    const uint32_t* kh = g_kh + (size_t)bh * NN * 32;
    const uint32_t* vh = g_vh + (size_t)bh * NN * 32;

    const int rr = lane >> 2;
    const int qq = lane & 3;

    uint32_t qf[2][4][4];
    #pragma unroll
    for (int mt = 0; mt < 2; mt++) {
        int rbase = q0 + w*32 + mt*16 + rr;
        #pragma unroll
        for (int ks = 0; ks < 4; ks++) {
            qf[mt][ks][0] = qh[(size_t)rbase*32     + ks*8 + qq];
            qf[mt][ks][1] = qh[(size_t)(rbase+8)*32 + ks*8 + qq];
            qf[mt][ks][2] = qh[(size_t)rbase*32     + ks*8 + qq + 4];
            qf[mt][ks][3] = qh[(size_t)(rbase+8)*32 + ks*8 + qq + 4];
        }
    }

    const int lm_base = (lane & 15)*KST + (lane >> 4)*4;

    auto issue = [&](int kt, int s) {
        const int k0 = kt * 64;
        #pragma unroll
        for (int i = 0; i < 4; i++) {
            int idx = tid + i*128;
            int r = idx >> 3, c4 = idx & 7;
            cp16(&Kh[s][r*KST + c4*4], kh + (size_t)(k0 + r)*32 + c4*4);
            cp16(&Vh[s][r*KST + c4*4], vh + (size_t)(k0 + r)*32 + c4*4);
        }
        CP_COMMIT();
    };

    float l_i[2][2];
    float o[2][8][4];
    #pragma unroll
    for (int mt = 0; mt < 2; mt++) {
        l_i[mt][0] = 0.f; l_i[mt][1] = 0.f;
        #pragma unroll
        for (int nt = 0; nt < 8; nt++)
            #pragma unroll
            for (int e = 0; e < 4; e++) o[mt][nt][e] = 0.f;
    }

    issue(0, 0);

    for (int kt = 0; kt < NN/64; kt++) {
        const int s = kt & 1;
        CP_WAIT(0);
        __syncthreads();
        if (kt + 1 < NN/64) issue(kt + 1, s ^ 1);

        // S for BOTH m-tiles in one pass (K frags loaded once)
        float sc[2][8][4];
        #pragma unroll
        for (int mt = 0; mt < 2; mt++)
            #pragma unroll
            for (int nt = 0; nt < 8; nt++)
                #pragma unroll
                for (int e = 0; e < 4; e++) sc[mt][nt][e] = 0.f;

        #pragma unroll
        for (int ks = 0; ks < 4; ks++) {
            #pragma unroll
            for (int nt = 0; nt < 8; nt++) {
                int cn = nt*8 + rr;
                uint32_t b0 = Kh[s][cn*KST + ks*8 + qq];
                uint32_t b1 = Kh[s][cn*KST + ks*8 + qq + 4];
                MMA_F16(sc[0][nt], qf[0][ks][0], qf[0][ks][1],
                                   qf[0][ks][2], qf[0][ks][3], b0, b1);
                MMA_F16(sc[1][nt], qf[1][ks][0], qf[1][ks][1],
                                   qf[1][ks][2], qf[1][ks][3], b0, b1);
            }
        }

        uint32_t ph[2][8][2];
        #pragma unroll
        for (int mt = 0; mt < 2; mt++) {
            float rs_lo = 0.f, rs_hi = 0.f;
            #pragma unroll
            for (int nt = 0; nt < 8; nt++) {
                float e0 = ex2(sc[mt][nt][0]);
                float e1 = ex2(sc[mt][nt][1]);
                float e2 = ex2(sc[mt][nt][2]);
                float e3 = ex2(sc[mt][nt][3]);
                rs_lo += e0 + e1;
                rs_hi += e2 + e3;
                ph[mt][nt][0] = f22u(e0, e1);
                ph[mt][nt][1] = f22u(e2, e3);
            }
            #pragma unroll
            for (int off = 1; off <= 2; off <<= 1) {
                rs_lo += __shfl_xor_sync(0xffffffffu, rs_lo, off);
                rs_hi += __shfl_xor_sync(0xffffffffu, rs_hi, off);
            }
            l_i[mt][0] += rs_lo;
            l_i[mt][1] += rs_hi;
        }

        // O += P @ V via ldmatrix.trans
        #pragma unroll
        for (int g = 0; g < 4; g++) {
            #pragma unroll
            for (int ntp = 0; ntp < 4; ntp++) {
                uint32_t b[4];
                uint32_t addr = (uint32_t)__cvta_generic_to_shared(
                    &Vh[s][g*16*KST + ntp*8 + lm_base]);
                LDSM_X4_T(b, addr);
                MMA_F16(o[0][2*ntp],   ph[0][2*g][0], ph[0][2*g][1],
                                       ph[0][2*g+1][0], ph[0][2*g+1][1], b[0], b[1]);
                MMA_F16(o[1][2*ntp],   ph[1][2*g][0], ph[1][2*g][1],
                                       ph[1][2*g+1][0], ph[1][2*g+1][1], b[0], b[1]);
                MMA_F16(o[0][2*ntp+1], ph[0][2*g][0], ph[0][2*g][1],
                                       ph[0][2*g+1][0], ph[0][2*g+1][1], b[2], b[3]);
                MMA_F16(o[1][2*ntp+1], ph[1][2*g][0], ph[1][2*g][1],
                                       ph[1][2*g+1][0], ph[1][2*g+1][1], b[2], b[3]);
            }
        }
    }

    // Finalize -> fp16 gathered layout
    const int b = bh >> 4, h = bh & 15;
    #pragma unroll
    for (int mt = 0; mt < 2; mt++) {
        float inv_lo = 1.f / l_i[mt][0], inv_hi = 1.f / l_i[mt][1];
        int r_lo = q0 + w*32 + mt*16 + rr;
        int r_hi = r_lo + 8;
        uint32_t* po_lo = g_oh + (size_t)(b*NN + r_lo)*512 + h*32;
        uint32_t* po_hi = g_oh + (size_t)(b*NN + r_hi)*512 + h*32;
        #pragma unroll
        for (int nt = 0; nt < 8; nt++) {
            int cu = nt*4 + qq;
            po_lo[cu] = f22u(o[mt][nt][0]*inv_lo, o[mt][nt][1]*inv_lo);
            po_hi[cu] = f22u(o[mt][nt][2]*inv_hi, o[mt][nt][3]*inv_hi);
        }
    }
}

// ---------------------------------------------------------------------------
extern "C" void kernel_launch(void* const* d_in, const int* in_sizes, int n_in,
                              void* d_out, int out_size)
{
    const float* x   = (const float*)d_in[0];
    const float* rc  = (const float*)d_in[1];
    const float* rs  = (const float*)d_in[2];
    const float* Wq  = (const float*)d_in[3];
    const float* bq  = (const float*)d_in[4];
    const float* Wk  = (const float*)d_in[5];
    const float* bk  = (const float*)d_in[6];
    const float* Wv  = (const float*)d_in[7];
    const float* bv  = (const float*)d_in[8];
    const float* qnw = (const float*)d_in[9];
    const float* qnb = (const float*)d_in[10];
    const float* knw = (const float*)d_in[11];
    const float* knb = (const float*)d_in[12];
    const float* Wo  = (const float*)d_in[13];
    const float* bo  = (const float*)d_in[14];
    float* out = (float*)d_out;

    cudaFuncSetAttribute(mm_mma,
                         cudaFuncAttributeMaxDynamicSharedMemorySize, MM_SMEM);

    cvt_all<<<6144, 256>>>(x, Wq, Wk, Wv, Wo);

    mm_mma<<<dim3(24, 32), 256, MM_SMEM>>>(0, bq, bk, bv, bo, out);

    const int warps2 = BB*HH*NN;               // (q+k rows) / 2 rows per warp
    ln_rope<<<warps2/8, 256>>>(qnw, qnb, knw, knb, rc, rs);

    attn_mma<<<dim3(NN/128, BB*HH), 128>>>();

    mm_mma<<<dim3(8, 32), 256, MM_SMEM>>>(1, bq, bk, bv, bo, out);
}